// round 1
// baseline (speedup 1.0000x reference)
#include <cuda_runtime.h>

// Problem constants
#define BB 4
#define NQ 16384
#define SS 2048
#define C1 128
#define C2 256
#define HH 256

// ---------------------------------------------------------------------------
// Device scratch (static __device__ arrays: allowed; no cudaMalloc anywhere)
// ---------------------------------------------------------------------------
__device__ float g_Z[BB * SS * HH];                 // Z = points2 @ W1b^T   (8 MB, L2-resident)
__device__ float g_buf[(size_t)BB * NQ * HH];       // pre (interp@W1b^T) -> h1, in place (64 MB)
__device__ float g_s1[HH], g_b1[HH], g_s2[HH], g_b2[HH];  // folded BN params

// ---------------------------------------------------------------------------
// Fold BatchNorm into scale/bias:  y = x*s + b,  s = gamma*rsqrt(rv+eps), b = beta - rm*s
// ---------------------------------------------------------------------------
__global__ void bn_prep(const float* __restrict__ g1, const float* __restrict__ be1,
                        const float* __restrict__ rm1, const float* __restrict__ rv1,
                        const float* __restrict__ g2, const float* __restrict__ be2,
                        const float* __restrict__ rm2, const float* __restrict__ rv2) {
    int h = threadIdx.x;
    float s1 = g1[h] * rsqrtf(rv1[h] + 1e-5f);
    g_s1[h] = s1;
    g_b1[h] = be1[h] - rm1[h] * s1;
    float s2 = g2[h] * rsqrtf(rv2[h] + 1e-5f);
    g_s2[h] = s2;
    g_b2[h] = be2[h] - rm2[h] * s2;
}

// ---------------------------------------------------------------------------
// 3-NN search + interpolation-gather.
// Each block: one batch b, 256 query points. xyz2 (+|c|^2) cached in smem.
// Ranking key: d2' = |c|^2 - 2 q.c  (same ordering as true distance).
// Phase 3 directly produces  pre[b,n,:] = sum_k w_k * Z[b, idx_k, :]
// ---------------------------------------------------------------------------
__global__ __launch_bounds__(256) void nn_interp(const float* __restrict__ xyz1,
                                                 const float* __restrict__ xyz2) {
    __shared__ __align__(16) float4 cand[SS];      // 32 KB
    __shared__ int   si[256][3];
    __shared__ float sw[256][3];

    const int b   = blockIdx.x;
    const int tid = threadIdx.x;

    // Phase 1: load candidates, precompute |c|^2
    const float* x2 = xyz2 + (size_t)b * SS * 3;
    for (int s = tid; s < SS; s += 256) {
        float x = x2[s * 3 + 0], y = x2[s * 3 + 1], z = x2[s * 3 + 2];
        cand[s] = make_float4(x, y, z, x * x + y * y + z * z);
    }
    __syncthreads();

    // Phase 2: scan 2048 candidates keeping 3 smallest (earliest index on ties)
    const int q = blockIdx.y * 256 + tid;
    const float* q3 = xyz1 + ((size_t)b * NQ + q) * 3;
    const float qx = q3[0], qy = q3[1], qz = q3[2];
    const float mx = -2.f * qx, my = -2.f * qy, mz = -2.f * qz;

    float d0 = 3.4e38f, d1 = 3.4e38f, d2 = 3.4e38f;
    int   i0 = 0, i1 = 0, i2 = 0;
#pragma unroll 4
    for (int s = 0; s < SS; s++) {
        float4 c = cand[s];
        float d = fmaf(mx, c.x, fmaf(my, c.y, fmaf(mz, c.z, c.w)));
        if (d < d2) {
            if (d < d1) {
                d2 = d1; i2 = i1;
                if (d < d0) { d1 = d0; i1 = i0; d0 = d; i0 = s; }
                else        { d1 = d;  i1 = s; }
            } else { d2 = d; i2 = s; }
        }
    }
    // true distances + inverse-distance weights (matches reference clamps)
    const float q2 = qx * qx + qy * qy + qz * qz;
    float t0 = sqrtf(fmaxf(d0 + q2, 0.f));
    float t1 = sqrtf(fmaxf(d1 + q2, 0.f));
    float t2 = sqrtf(fmaxf(d2 + q2, 0.f));
    float w0 = 1.f / fmaxf(t0, 1e-10f);
    float w1 = 1.f / fmaxf(t1, 1e-10f);
    float w2 = 1.f / fmaxf(t2, 1e-10f);
    float inv = 1.f / (w0 + w1 + w2);
    si[tid][0] = i0; si[tid][1] = i1; si[tid][2] = i2;
    sw[tid][0] = w0 * inv; sw[tid][1] = w1 * inv; sw[tid][2] = w2 * inv;
    __syncthreads();

    // Phase 3: gather 3 Z rows per query, weighted sum -> g_buf (coalesced float4)
    const int grp  = tid >> 6;     // 4 groups of 64 lanes
    const int lane = tid & 63;     // 64 lanes * float4 = 256 floats = one H row
    const float4* Zb = (const float4*)(g_Z + (size_t)b * SS * HH);
    float4* outb = (float4*)(g_buf + ((size_t)b * NQ + (size_t)blockIdx.y * 256) * HH);
    for (int ql = grp; ql < 256; ql += 4) {
        int   a0 = si[ql][0], a1 = si[ql][1], a2 = si[ql][2];
        float u0 = sw[ql][0], u1 = sw[ql][1], u2 = sw[ql][2];
        float4 z0 = Zb[a0 * 64 + lane];
        float4 z1 = Zb[a1 * 64 + lane];
        float4 z2 = Zb[a2 * 64 + lane];
        float4 r;
        r.x = fmaf(u0, z0.x, fmaf(u1, z1.x, u2 * z2.x));
        r.y = fmaf(u0, z0.y, fmaf(u1, z1.y, u2 * z2.y));
        r.z = fmaf(u0, z0.z, fmaf(u1, z1.z, u2 * z2.z));
        r.w = fmaf(u0, z0.w, fmaf(u1, z1.w, u2 * z2.w));
        outb[ql * 64 + lane] = r;
    }
}

// ---------------------------------------------------------------------------
// Tiled fp32 SIMT GEMM:  out[M,256] = A[M,K] @ W[256,K]^T (+epilogue)
//   MODE 0: A=param(points2), out=g_Z,  plain store            (Z precompute)
//   MODE 1: A=param(points1), out=g_buf, out=(acc+pre)*s1+b1, ReLU (pre==g_buf, in place)
//   MODE 2: A=g_buf,          out=param, out=acc*s2+b2, ReLU
// Tiles: BM=BN=128, BK=8; 256 threads; 8x8 per thread.
// ---------------------------------------------------------------------------
template <int MODE>
__global__ __launch_bounds__(256) void gemm_bn(const float* __restrict__ Ain, int lda, int K,
                                               const float* __restrict__ W, int ldw,
                                               float* __restrict__ outp) {
    __shared__ __align__(16) float As[8][128];
    __shared__ __align__(16) float Ws[8][128];

    const int tid  = threadIdx.x;
    const int row0 = blockIdx.x * 128;
    const int col0 = blockIdx.y * 128;
    const int lr = tid >> 1;            // 0..127 : tile row (A) / tile col (W)
    const int ls = (tid & 1) * 4;       // k-segment (float4)
    const int tr = tid >> 4;            // 0..15 : 8-row group
    const int tc = tid & 15;            // 0..15 : 8-col group

    const float* A = (MODE == 2) ? g_buf : Ain;
    const float* Ap = A + (size_t)(row0 + lr) * lda + ls;
    const float* Wp = W + (size_t)(col0 + lr) * ldw + ls;

    float acc[8][8];
#pragma unroll
    for (int i = 0; i < 8; i++)
#pragma unroll
        for (int j = 0; j < 8; j++) acc[i][j] = 0.f;

    for (int k0 = 0; k0 < K; k0 += 8) {
        float4 av = *(const float4*)(Ap + k0);
        float4 wv = *(const float4*)(Wp + k0);
        __syncthreads();
        As[ls + 0][lr] = av.x; As[ls + 1][lr] = av.y;
        As[ls + 2][lr] = av.z; As[ls + 3][lr] = av.w;
        Ws[ls + 0][lr] = wv.x; Ws[ls + 1][lr] = wv.y;
        Ws[ls + 2][lr] = wv.z; Ws[ls + 3][lr] = wv.w;
        __syncthreads();
#pragma unroll
        for (int k = 0; k < 8; k++) {
            float4 a0 = *(const float4*)&As[k][tr * 8];
            float4 a1 = *(const float4*)&As[k][tr * 8 + 4];
            float4 b0 = *(const float4*)&Ws[k][tc * 8];
            float4 b1 = *(const float4*)&Ws[k][tc * 8 + 4];
            float am[8] = {a0.x, a0.y, a0.z, a0.w, a1.x, a1.y, a1.z, a1.w};
            float bn[8] = {b0.x, b0.y, b0.z, b0.w, b1.x, b1.y, b1.z, b1.w};
#pragma unroll
            for (int i = 0; i < 8; i++)
#pragma unroll
                for (int j = 0; j < 8; j++)
                    acc[i][j] = fmaf(am[i], bn[j], acc[i][j]);
        }
    }

    // Epilogue
    float* obase = (MODE == 0) ? g_Z : (MODE == 1) ? g_buf : outp;
    float4 sc0, sc1, bi0, bi1;
    if (MODE != 0) {
        const float* sc = (MODE == 1) ? g_s1 : g_s2;
        const float* bi = (MODE == 1) ? g_b1 : g_b2;
        sc0 = *(const float4*)&sc[col0 + tc * 8];
        sc1 = *(const float4*)&sc[col0 + tc * 8 + 4];
        bi0 = *(const float4*)&bi[col0 + tc * 8];
        bi1 = *(const float4*)&bi[col0 + tc * 8 + 4];
    }
    const float s[8] = {sc0.x, sc0.y, sc0.z, sc0.w, sc1.x, sc1.y, sc1.z, sc1.w};
    const float t[8] = {bi0.x, bi0.y, bi0.z, bi0.w, bi1.x, bi1.y, bi1.z, bi1.w};

#pragma unroll
    for (int i = 0; i < 8; i++) {
        int r = row0 + tr * 8 + i;
        float* orow = obase + (size_t)r * HH + col0 + tc * 8;
        if (MODE == 0) {
            float4 v0 = {acc[i][0], acc[i][1], acc[i][2], acc[i][3]};
            float4 v1 = {acc[i][4], acc[i][5], acc[i][6], acc[i][7]};
            *(float4*)orow       = v0;
            *(float4*)(orow + 4) = v1;
        } else {
            float v[8];
            if (MODE == 1) {
                float4 p0 = *(const float4*)orow;
                float4 p1 = *(const float4*)(orow + 4);
                float p[8] = {p0.x, p0.y, p0.z, p0.w, p1.x, p1.y, p1.z, p1.w};
#pragma unroll
                for (int j = 0; j < 8; j++)
                    v[j] = fmaxf(fmaf(acc[i][j] + p[j], s[j], t[j]), 0.f);
            } else {
#pragma unroll
                for (int j = 0; j < 8; j++)
                    v[j] = fmaxf(fmaf(acc[i][j], s[j], t[j]), 0.f);
            }
            float4 v0 = {v[0], v[1], v[2], v[3]};
            float4 v1 = {v[4], v[5], v[6], v[7]};
            *(float4*)orow       = v0;
            *(float4*)(orow + 4) = v1;
        }
    }
}

// ---------------------------------------------------------------------------
// Launch: bn_prep -> Z -> NN+gather -> GEMM1(+pre,BN,ReLU) -> GEMM2(BN,ReLU)
// All on the default stream; graph-capturable (launches only).
// ---------------------------------------------------------------------------
extern "C" void kernel_launch(void* const* d_in, const int* in_sizes, int n_in,
                              void* d_out, int out_size) {
    const float* xyz1    = (const float*)d_in[0];
    const float* xyz2    = (const float*)d_in[1];
    const float* points1 = (const float*)d_in[2];
    const float* points2 = (const float*)d_in[3];
    const float* W1      = (const float*)d_in[4];
    const float* gamma1  = (const float*)d_in[5];
    const float* beta1   = (const float*)d_in[6];
    const float* rm1     = (const float*)d_in[7];
    const float* rv1     = (const float*)d_in[8];
    const float* W2      = (const float*)d_in[9];
    const float* gamma2  = (const float*)d_in[10];
    const float* beta2   = (const float*)d_in[11];
    const float* rm2     = (const float*)d_in[12];
    const float* rv2     = (const float*)d_in[13];
    float* out = (float*)d_out;

    bn_prep<<<1, HH>>>(gamma1, beta1, rm1, rv1, gamma2, beta2, rm2, rv2);

    // K0: Z[b,s,h] = points2 @ W1b^T   (W1 cols 128..383)
    gemm_bn<0><<<dim3(BB * SS / 128, 2), 256>>>(points2, C2, C2, W1 + C1, C1 + C2, nullptr);

    // NN + interpolation gather -> g_buf (pre)
    nn_interp<<<dim3(BB, NQ / 256), 256>>>(xyz1, xyz2);

    // K2: h1 = relu(bn1(points1 @ W1a^T + pre))   (in place on g_buf)
    gemm_bn<1><<<dim3(BB * NQ / 128, 2), 256>>>(points1, C1, C1, W1, C1 + C2, nullptr);

    // K3: out = relu(bn2(h1 @ W2^T))
    gemm_bn<2><<<dim3(BB * NQ / 128, 2), 256>>>(nullptr, HH, HH, W2, HH, out);
}

// round 3
// speedup vs baseline: 1.6089x; 1.6089x over previous
#include <cuda_runtime.h>
#include <cuda_bf16.h>
#include <cstdint>

// Problem constants
#define BB 4
#define NQ 16384
#define SS 2048
#define C1 128
#define C2 256
#define HH 256
#define MROWS (BB * NQ)   // 65536
#define SROWS (BB * SS)   // 8192

// ---------------------------------------------------------------------------
// Device scratch
// ---------------------------------------------------------------------------
__device__ float g_Z[SROWS * HH];                 // Z = points2 @ W1b^T (fp32, 8MB)
__device__ float g_pre[(size_t)MROWS * HH];       // interp @ W1b^T     (fp32, 64MB)
__device__ float g_h1[(size_t)MROWS * HH];        // h1                  (fp32, 64MB)
__device__ float g_s1[HH], g_b1[HH], g_s2[HH], g_b2[HH];

// ---------------------------------------------------------------------------
// Helpers
// ---------------------------------------------------------------------------
__device__ __forceinline__ uint32_t smem_u32(const void* p) {
    uint32_t a;
    asm("{ .reg .u64 t; cvta.to.shared.u64 t, %1; cvt.u32.u64 %0, t; }" : "=r"(a) : "l"(p));
    return a;
}

__device__ __forceinline__ void ldm4(uint32_t* r, uint32_t addr) {
    asm volatile("ldmatrix.sync.aligned.m8n8.x4.shared.b16 {%0,%1,%2,%3}, [%4];"
                 : "=r"(r[0]), "=r"(r[1]), "=r"(r[2]), "=r"(r[3]) : "r"(addr));
}

__device__ __forceinline__ void mma16816(float* c, const uint32_t* a, const uint32_t* b) {
    asm volatile(
        "mma.sync.aligned.m16n8k16.row.col.f32.bf16.bf16.f32 "
        "{%0,%1,%2,%3}, {%4,%5,%6,%7}, {%8,%9}, {%0,%1,%2,%3};"
        : "+f"(c[0]), "+f"(c[1]), "+f"(c[2]), "+f"(c[3])
        : "r"(a[0]), "r"(a[1]), "r"(a[2]), "r"(a[3]), "r"(b[0]), "r"(b[1]));
}

// pack 2 bf16 -> u32
__device__ __forceinline__ uint32_t pack2(__nv_bfloat16 a, __nv_bfloat16 b) {
    return (uint32_t)__bfloat16_as_ushort(a) | ((uint32_t)__bfloat16_as_ushort(b) << 16);
}
// 4 floats -> hi u32x2 / lo u32x2
__device__ __forceinline__ void split4(float4 v, uint32_t* hi, uint32_t* lo) {
    __nv_bfloat16 h0 = __float2bfloat16_rn(v.x);
    __nv_bfloat16 h1 = __float2bfloat16_rn(v.y);
    __nv_bfloat16 h2 = __float2bfloat16_rn(v.z);
    __nv_bfloat16 h3 = __float2bfloat16_rn(v.w);
    __nv_bfloat16 l0 = __float2bfloat16_rn(v.x - __bfloat162float(h0));
    __nv_bfloat16 l1 = __float2bfloat16_rn(v.y - __bfloat162float(h1));
    __nv_bfloat16 l2 = __float2bfloat16_rn(v.z - __bfloat162float(h2));
    __nv_bfloat16 l3 = __float2bfloat16_rn(v.w - __bfloat162float(h3));
    hi[0] = pack2(h0, h1); hi[1] = pack2(h2, h3);
    lo[0] = pack2(l0, l1); lo[1] = pack2(l2, l3);
}

// swizzled byte offset inside a 128row x 128B tile
__device__ __forceinline__ uint32_t sw(uint32_t row, uint32_t kb) {
    return row * 128u + (kb ^ ((row & 7u) << 4));
}

// ---------------------------------------------------------------------------
// BN fold
// ---------------------------------------------------------------------------
__global__ void bn_prep(const float* __restrict__ g1, const float* __restrict__ be1,
                        const float* __restrict__ rm1, const float* __restrict__ rv1,
                        const float* __restrict__ g2, const float* __restrict__ be2,
                        const float* __restrict__ rm2, const float* __restrict__ rv2) {
    int h = threadIdx.x;
    float s1 = g1[h] * rsqrtf(rv1[h] + 1e-5f);
    g_s1[h] = s1; g_b1[h] = be1[h] - rm1[h] * s1;
    float s2 = g2[h] * rsqrtf(rv2[h] + 1e-5f);
    g_s2[h] = s2; g_b2[h] = be2[h] - rm2[h] * s2;
}

// ---------------------------------------------------------------------------
// 3-NN search + interpolation-gather  (writes g_pre)
// ---------------------------------------------------------------------------
__global__ __launch_bounds__(256) void nn_interp(const float* __restrict__ xyz1,
                                                 const float* __restrict__ xyz2) {
    __shared__ __align__(16) float4 cand[SS];
    __shared__ int   si[256][3];
    __shared__ float swt[256][3];

    const int b = blockIdx.x, tid = threadIdx.x;
    const float* x2 = xyz2 + (size_t)b * SS * 3;
    for (int s = tid; s < SS; s += 256) {
        float x = x2[s * 3 + 0], y = x2[s * 3 + 1], z = x2[s * 3 + 2];
        cand[s] = make_float4(x, y, z, x * x + y * y + z * z);
    }
    __syncthreads();

    const int q = blockIdx.y * 256 + tid;
    const float* q3 = xyz1 + ((size_t)b * NQ + q) * 3;
    const float qx = q3[0], qy = q3[1], qz = q3[2];
    const float mx = -2.f * qx, my = -2.f * qy, mz = -2.f * qz;

    float d0 = 3.4e38f, d1 = 3.4e38f, d2 = 3.4e38f;
    int i0 = 0, i1 = 0, i2 = 0;
#pragma unroll 4
    for (int s = 0; s < SS; s++) {
        float4 c = cand[s];
        float d = fmaf(mx, c.x, fmaf(my, c.y, fmaf(mz, c.z, c.w)));
        if (d < d2) {
            if (d < d1) {
                d2 = d1; i2 = i1;
                if (d < d0) { d1 = d0; i1 = i0; d0 = d; i0 = s; }
                else        { d1 = d;  i1 = s; }
            } else { d2 = d; i2 = s; }
        }
    }
    const float q2 = qx * qx + qy * qy + qz * qz;
    float t0 = sqrtf(fmaxf(d0 + q2, 0.f));
    float t1 = sqrtf(fmaxf(d1 + q2, 0.f));
    float t2 = sqrtf(fmaxf(d2 + q2, 0.f));
    float w0 = 1.f / fmaxf(t0, 1e-10f);
    float w1 = 1.f / fmaxf(t1, 1e-10f);
    float w2 = 1.f / fmaxf(t2, 1e-10f);
    float inv = 1.f / (w0 + w1 + w2);
    si[tid][0] = i0; si[tid][1] = i1; si[tid][2] = i2;
    swt[tid][0] = w0 * inv; swt[tid][1] = w1 * inv; swt[tid][2] = w2 * inv;
    __syncthreads();

    const int grp = tid >> 6, lane = tid & 63;
    const float4* Zb = (const float4*)(g_Z + (size_t)b * SS * HH);
    float4* outb = (float4*)(g_pre + ((size_t)b * NQ + (size_t)blockIdx.y * 256) * HH);
    for (int ql = grp; ql < 256; ql += 4) {
        int   a0 = si[ql][0], a1 = si[ql][1], a2 = si[ql][2];
        float u0 = swt[ql][0], u1 = swt[ql][1], u2 = swt[ql][2];
        float4 z0 = Zb[a0 * 64 + lane];
        float4 z1 = Zb[a1 * 64 + lane];
        float4 z2 = Zb[a2 * 64 + lane];
        float4 r;
        r.x = fmaf(u0, z0.x, fmaf(u1, z1.x, u2 * z2.x));
        r.y = fmaf(u0, z0.y, fmaf(u1, z1.y, u2 * z2.y));
        r.z = fmaf(u0, z0.z, fmaf(u1, z1.z, u2 * z2.z));
        r.w = fmaf(u0, z0.w, fmaf(u1, z1.w, u2 * z2.w));
        outb[ql * 64 + lane] = r;
    }
}

// ---------------------------------------------------------------------------
// HMMA GEMM (mma.sync bf16, 3-term split, on-the-fly fp32->hi/lo conversion)
//   out[M,256] = A[M,K] @ W[256,K]^T (+epilogue)
//   MODE 0: A=points2 (K=256, ldw=384) -> g_Z (plain fp32)
//   MODE 1: A=points1 (K=128, ldw=384) -> g_h1 = relu(bn1(acc + g_pre))
//   MODE 2: A=g_h1    (K=256, ldw=256) -> out  = relu(bn2(acc))
// CTA tile 128x128, BK=64. 8 warps, each 64(m) x 32(n).
// smem: 4 bf16 tiles (A_hi, A_lo, B_hi, B_lo), 128 rows x 128B, SW128 swizzle.
// ---------------------------------------------------------------------------
#define TILEB 16384
#define SMEM_SZ (4 * TILEB)

template <int MODE>
__global__ __launch_bounds__(256, 2) void mma_gemm(const float* __restrict__ Ain,
                                                   const float* __restrict__ Bw,
                                                   float* __restrict__ outp) {
    extern __shared__ char smem[];
    constexpr int KK  = (MODE == 1) ? C1 : C2;
    constexpr int LDW = (MODE == 2) ? HH : (C1 + C2);
    constexpr int NCH = KK / 64;

    const int tid = threadIdx.x, wid = tid >> 5, lane = tid & 31;
    const int row0 = blockIdx.x * 128, col0 = blockIdx.y * 128;
    const int wm = wid & 1, wn = wid >> 1;      // warp tile: rows wm*64, cols wn*32

    const float* A = (MODE == 2) ? g_h1 : Ain;

    const uint32_t sA_h = smem_u32(smem);
    const uint32_t sA_l = sA_h + TILEB;
    const uint32_t sB_h = sA_h + 2 * TILEB;
    const uint32_t sB_l = sA_h + 3 * TILEB;

    // ldmatrix per-lane bases
    const int j   = lane >> 3;          // matrix index 0..3
    const int jlo = j & 1, jhi = j >> 1;
    const uint32_t xr = (uint32_t)(lane & 7) << 4;
    const uint32_t aRow = (uint32_t)(wm * 64 + jlo * 8 + (lane & 7)) * 128u;
    const uint32_t bRow = (uint32_t)(wn * 32 + jlo * 8 + (lane & 7)) * 128u;

    float acc[4][4][4];
#pragma unroll
    for (int mt = 0; mt < 4; mt++)
#pragma unroll
        for (int nt = 0; nt < 4; nt++)
#pragma unroll
            for (int e = 0; e < 4; e++) acc[mt][nt][e] = 0.f;

    // smem store mapping: 512 16B-segments per matrix, 2 per thread
    const int s0 = tid, s1 = tid + 256;   // seg = row*4 + sg

    for (int c = 0; c < NCH; c++) {
        if (c) __syncthreads();
        // ---- load fp32, split, store swizzled bf16 tiles ----
#pragma unroll
        for (int it = 0; it < 2; it++) {
            const int seg = it ? s1 : s0;
            const int row = seg >> 2, sg = seg & 3;
            const size_t ga = (size_t)(row0 + row) * KK + c * 64 + sg * 16;
            const size_t gb = (size_t)(col0 + row) * LDW + c * 64 + sg * 16;
            float4 a0 = *(const float4*)(A + ga);
            float4 a1 = *(const float4*)(A + ga + 4);
            float4 a2 = *(const float4*)(A + ga + 8);
            float4 a3 = *(const float4*)(A + ga + 12);
            float4 b0 = *(const float4*)(Bw + gb);
            float4 b1 = *(const float4*)(Bw + gb + 4);
            float4 b2 = *(const float4*)(Bw + gb + 8);
            float4 b3 = *(const float4*)(Bw + gb + 12);
            uint32_t h[8], l[8];
            const uint32_t so0 = sw((uint32_t)row, (uint32_t)sg * 32u);
            const uint32_t so1 = sw((uint32_t)row, (uint32_t)sg * 32u + 16u);
            split4(a0, h + 0, l + 0); split4(a1, h + 2, l + 2);
            split4(a2, h + 4, l + 4); split4(a3, h + 6, l + 6);
            *(uint4*)(smem + (sA_h - smem_u32(smem)) + so0) = make_uint4(h[0], h[1], h[2], h[3]);
            *(uint4*)(smem + (sA_h - smem_u32(smem)) + so1) = make_uint4(h[4], h[5], h[6], h[7]);
            *(uint4*)(smem + (sA_l - smem_u32(smem)) + so0) = make_uint4(l[0], l[1], l[2], l[3]);
            *(uint4*)(smem + (sA_l - smem_u32(smem)) + so1) = make_uint4(l[4], l[5], l[6], l[7]);
            split4(b0, h + 0, l + 0); split4(b1, h + 2, l + 2);
            split4(b2, h + 4, l + 4); split4(b3, h + 6, l + 6);
            *(uint4*)(smem + (sB_h - smem_u32(smem)) + so0) = make_uint4(h[0], h[1], h[2], h[3]);
            *(uint4*)(smem + (sB_h - smem_u32(smem)) + so1) = make_uint4(h[4], h[5], h[6], h[7]);
            *(uint4*)(smem + (sB_l - smem_u32(smem)) + so0) = make_uint4(l[0], l[1], l[2], l[3]);
            *(uint4*)(smem + (sB_l - smem_u32(smem)) + so1) = make_uint4(l[4], l[5], l[6], l[7]);
        }
        __syncthreads();

        // ---- compute: 4 ksteps of k=16; splits hh, hl, lh ----
#pragma unroll
        for (int ks = 0; ks < 4; ks++) {
            const uint32_t kb = ((uint32_t)(ks * 32 + jhi * 16)) ^ xr;
            uint32_t ah[4][4], bh[4][2], bl[4][2];
#pragma unroll
            for (int mt = 0; mt < 4; mt++)
                ldm4(ah[mt], sA_h + aRow + mt * 2048u + kb);
#pragma unroll
            for (int p = 0; p < 2; p++) {
                uint32_t r[4];
                ldm4(r, sB_h + bRow + p * 2048u + kb);
                bh[p * 2 + 0][0] = r[0]; bh[p * 2 + 0][1] = r[2];
                bh[p * 2 + 1][0] = r[1]; bh[p * 2 + 1][1] = r[3];
                ldm4(r, sB_l + bRow + p * 2048u + kb);
                bl[p * 2 + 0][0] = r[0]; bl[p * 2 + 0][1] = r[2];
                bl[p * 2 + 1][0] = r[1]; bl[p * 2 + 1][1] = r[3];
            }
#pragma unroll
            for (int mt = 0; mt < 4; mt++)
#pragma unroll
                for (int nt = 0; nt < 4; nt++) {
                    mma16816(acc[mt][nt], ah[mt], bh[nt]);
                    mma16816(acc[mt][nt], ah[mt], bl[nt]);
                }
            uint32_t al[4][4];
#pragma unroll
            for (int mt = 0; mt < 4; mt++)
                ldm4(al[mt], sA_l + aRow + mt * 2048u + kb);
#pragma unroll
            for (int mt = 0; mt < 4; mt++)
#pragma unroll
                for (int nt = 0; nt < 4; nt++)
                    mma16816(acc[mt][nt], al[mt], bh[nt]);
        }
    }

    // ---- epilogue ----
    const int g = lane >> 2, t = lane & 3;
#pragma unroll
    for (int mt = 0; mt < 4; mt++) {
        const int ra = row0 + wm * 64 + mt * 16 + g;
        const int rb = ra + 8;
#pragma unroll
        for (int nt = 0; nt < 4; nt++) {
            const int col = col0 + wn * 32 + nt * 8 + 2 * t;
            float v0 = acc[mt][nt][0], v1 = acc[mt][nt][1];
            float v2 = acc[mt][nt][2], v3 = acc[mt][nt][3];
            if (MODE == 0) {
                *(float2*)(g_Z + (size_t)ra * HH + col) = make_float2(v0, v1);
                *(float2*)(g_Z + (size_t)rb * HH + col) = make_float2(v2, v3);
            } else if (MODE == 1) {
                float2 pa = *(const float2*)(g_pre + (size_t)ra * HH + col);
                float2 pb = *(const float2*)(g_pre + (size_t)rb * HH + col);
                float sc0 = g_s1[col], sc1 = g_s1[col + 1];
                float bb0 = g_b1[col], bb1 = g_b1[col + 1];
                v0 = fmaxf(fmaf(v0 + pa.x, sc0, bb0), 0.f);
                v1 = fmaxf(fmaf(v1 + pa.y, sc1, bb1), 0.f);
                v2 = fmaxf(fmaf(v2 + pb.x, sc0, bb0), 0.f);
                v3 = fmaxf(fmaf(v3 + pb.y, sc1, bb1), 0.f);
                *(float2*)(g_h1 + (size_t)ra * HH + col) = make_float2(v0, v1);
                *(float2*)(g_h1 + (size_t)rb * HH + col) = make_float2(v2, v3);
            } else {
                float sc0 = g_s2[col], sc1 = g_s2[col + 1];
                float bb0 = g_b2[col], bb1 = g_b2[col + 1];
                v0 = fmaxf(fmaf(v0, sc0, bb0), 0.f);
                v1 = fmaxf(fmaf(v1, sc1, bb1), 0.f);
                v2 = fmaxf(fmaf(v2, sc0, bb0), 0.f);
                v3 = fmaxf(fmaf(v3, sc1, bb1), 0.f);
                *(float2*)(outp + (size_t)ra * HH + col) = make_float2(v0, v1);
                *(float2*)(outp + (size_t)rb * HH + col) = make_float2(v2, v3);
            }
        }
    }
}

// ---------------------------------------------------------------------------
// Launch
// ---------------------------------------------------------------------------
extern "C" void kernel_launch(void* const* d_in, const int* in_sizes, int n_in,
                              void* d_out, int out_size) {
    const float* xyz1    = (const float*)d_in[0];
    const float* xyz2    = (const float*)d_in[1];
    const float* points1 = (const float*)d_in[2];
    const float* points2 = (const float*)d_in[3];
    const float* W1      = (const float*)d_in[4];
    const float* gamma1  = (const float*)d_in[5];
    const float* beta1   = (const float*)d_in[6];
    const float* rm1     = (const float*)d_in[7];
    const float* rv1     = (const float*)d_in[8];
    const float* W2      = (const float*)d_in[9];
    const float* gamma2  = (const float*)d_in[10];
    const float* beta2   = (const float*)d_in[11];
    const float* rm2     = (const float*)d_in[12];
    const float* rv2     = (const float*)d_in[13];
    float* out = (float*)d_out;

    cudaFuncSetAttribute(mma_gemm<0>, cudaFuncAttributeMaxDynamicSharedMemorySize, SMEM_SZ);
    cudaFuncSetAttribute(mma_gemm<1>, cudaFuncAttributeMaxDynamicSharedMemorySize, SMEM_SZ);
    cudaFuncSetAttribute(mma_gemm<2>, cudaFuncAttributeMaxDynamicSharedMemorySize, SMEM_SZ);

    bn_prep<<<1, HH>>>(gamma1, beta1, rm1, rv1, gamma2, beta2, rm2, rv2);

    // Z = points2 @ W1b^T  (W1 cols 128..383)
    mma_gemm<0><<<dim3(SROWS / 128, 2), 256, SMEM_SZ>>>(points2, W1 + C1, nullptr);

    // 3-NN + interpolation gather -> g_pre
    nn_interp<<<dim3(BB, NQ / 256), 256>>>(xyz1, xyz2);

    // h1 = relu(bn1(points1 @ W1a^T + pre))
    mma_gemm<1><<<dim3(MROWS / 128, 2), 256, SMEM_SZ>>>(points1, W1, nullptr);

    // out = relu(bn2(h1 @ W2^T))
    mma_gemm<2><<<dim3(MROWS / 128, 2), 256, SMEM_SZ>>>(nullptr, W2, out);
}

// round 7
// speedup vs baseline: 1.6630x; 1.0336x over previous
#include <cuda_runtime.h>
#include <cuda_bf16.h>
#include <cstdint>

// Problem constants
#define BB 4
#define NQ 16384
#define SS 2048
#define C1 128
#define C2 256
#define HH 256
#define MROWS (BB * NQ)   // 65536
#define SROWS (BB * SS)   // 8192

// ---------------------------------------------------------------------------
// Device scratch
// ---------------------------------------------------------------------------
__device__ float g_Z[SROWS * HH];                       // 8MB, L2-resident
__device__ __nv_bfloat16 g_h1h[(size_t)MROWS * HH];     // h1 hi, tiled+swizzled (32MB)
__device__ __nv_bfloat16 g_h1l[(size_t)MROWS * HH];     // h1 lo, tiled+swizzled (32MB)
__device__ int4   g_idx[MROWS];                         // 3-NN indices (GLOBAL: b*SS+s)
__device__ float4 g_wt[MROWS];                          // 3-NN weights (normalized)
// weights pre-split, tiled+swizzled: [chunk][n(=out col) 256 rows][64 k, SW128]
__device__ __nv_bfloat16 g_w1a_h[HH * C1], g_w1a_l[HH * C1];
__device__ __nv_bfloat16 g_w1b_h[HH * C2], g_w1b_l[HH * C2];
__device__ __nv_bfloat16 g_w2_h[HH * HH],  g_w2_l[HH * HH];
__device__ float g_s1[HH], g_b1[HH], g_s2[HH], g_b2[HH];

// ---------------------------------------------------------------------------
// Helpers
// ---------------------------------------------------------------------------
__device__ __forceinline__ uint32_t smem_u32(const void* p) {
    uint32_t a;
    asm("{ .reg .u64 t; cvta.to.shared.u64 t, %1; cvt.u32.u64 %0, t; }" : "=r"(a) : "l"(p));
    return a;
}
__device__ __forceinline__ void ldm4(uint32_t* r, uint32_t addr) {
    asm volatile("ldmatrix.sync.aligned.m8n8.x4.shared.b16 {%0,%1,%2,%3}, [%4];"
                 : "=r"(r[0]), "=r"(r[1]), "=r"(r[2]), "=r"(r[3]) : "r"(addr));
}
__device__ __forceinline__ void mma16816(float* c, const uint32_t* a, const uint32_t* b) {
    asm volatile(
        "mma.sync.aligned.m16n8k16.row.col.f32.bf16.bf16.f32 "
        "{%0,%1,%2,%3}, {%4,%5,%6,%7}, {%8,%9}, {%0,%1,%2,%3};"
        : "+f"(c[0]), "+f"(c[1]), "+f"(c[2]), "+f"(c[3])
        : "r"(a[0]), "r"(a[1]), "r"(a[2]), "r"(a[3]), "r"(b[0]), "r"(b[1]));
}
__device__ __forceinline__ void cp16(uint32_t dst, const void* src) {
    asm volatile("cp.async.cg.shared.global [%0], [%1], 16;" :: "r"(dst), "l"(src));
}
#define CP_COMMIT() asm volatile("cp.async.commit_group;" ::: "memory")
#define CP_WAIT()   asm volatile("cp.async.wait_group 0;" ::: "memory")

__device__ __forceinline__ uint32_t pack2(__nv_bfloat16 a, __nv_bfloat16 b) {
    return (uint32_t)__bfloat16_as_ushort(a) | ((uint32_t)__bfloat16_as_ushort(b) << 16);
}
__device__ __forceinline__ void split4(float4 v, uint32_t* hi, uint32_t* lo) {
    __nv_bfloat16 h0 = __float2bfloat16_rn(v.x);
    __nv_bfloat16 h1 = __float2bfloat16_rn(v.y);
    __nv_bfloat16 h2 = __float2bfloat16_rn(v.z);
    __nv_bfloat16 h3 = __float2bfloat16_rn(v.w);
    __nv_bfloat16 l0 = __float2bfloat16_rn(v.x - __bfloat162float(h0));
    __nv_bfloat16 l1 = __float2bfloat16_rn(v.y - __bfloat162float(h1));
    __nv_bfloat16 l2 = __float2bfloat16_rn(v.z - __bfloat162float(h2));
    __nv_bfloat16 l3 = __float2bfloat16_rn(v.w - __bfloat162float(h3));
    hi[0] = pack2(h0, h1); hi[1] = pack2(h2, h3);
    lo[0] = pack2(l0, l1); lo[1] = pack2(l2, l3);
}
// swizzled byte offset within a [rows x 128B] tile
__device__ __forceinline__ uint32_t sw(uint32_t row, uint32_t kb) {
    return row * 128u + (kb ^ ((row & 7u) << 4));
}

// ---------------------------------------------------------------------------
// BN fold
// ---------------------------------------------------------------------------
__global__ void bn_prep(const float* __restrict__ g1, const float* __restrict__ be1,
                        const float* __restrict__ rm1, const float* __restrict__ rv1,
                        const float* __restrict__ g2, const float* __restrict__ be2,
                        const float* __restrict__ rm2, const float* __restrict__ rv2) {
    int h = threadIdx.x;
    float s1 = g1[h] * rsqrtf(rv1[h] + 1e-5f);
    g_s1[h] = s1; g_b1[h] = be1[h] - rm1[h] * s1;
    float s2 = g2[h] * rsqrtf(rv2[h] + 1e-5f);
    g_s2[h] = s2; g_b2[h] = be2[h] - rm2[h] * s2;
}

// ---------------------------------------------------------------------------
// Weight split into tiled+swizzled bf16 hi/lo
// ---------------------------------------------------------------------------
__global__ __launch_bounds__(256) void split_weights(const float* __restrict__ W1,
                                                     const float* __restrict__ W2) {
    int i = blockIdx.x * 256 + threadIdx.x;   // 163840 total
    float v; __nv_bfloat16 *H, *L; int n, k;
    if (i < 32768)       { n = i >> 7; k = i & 127; v = W1[n * 384 + k];       H = g_w1a_h; L = g_w1a_l; }
    else if (i < 98304)  { int j = i - 32768; n = j >> 8; k = j & 255; v = W1[n * 384 + 128 + k]; H = g_w1b_h; L = g_w1b_l; }
    else                 { int j = i - 98304; n = j >> 8; k = j & 255; v = W2[n * 256 + k];       H = g_w2_h;  L = g_w2_l; }
    __nv_bfloat16 h = __float2bfloat16_rn(v);
    __nv_bfloat16 l = __float2bfloat16_rn(v - __bfloat162float(h));
    int chunk = k >> 6, kin = k & 63;
    int boff = n * 128 + ((kin * 2) ^ ((n & 7) << 4));
    int off = chunk * 16384 + (boff >> 1);
    H[off] = h; L[off] = l;
}

// ---------------------------------------------------------------------------
// 3-NN search: writes GLOBAL idx (b*SS + s) + normalized weights
// ---------------------------------------------------------------------------
__global__ __launch_bounds__(256) void nn_idx(const float* __restrict__ xyz1,
                                              const float* __restrict__ xyz2) {
    __shared__ __align__(16) float4 cand[SS];
    const int b = blockIdx.x, tid = threadIdx.x;
    const float* x2 = xyz2 + (size_t)b * SS * 3;
    for (int s = tid; s < SS; s += 256) {
        float x = x2[s * 3 + 0], y = x2[s * 3 + 1], z = x2[s * 3 + 2];
        cand[s] = make_float4(x, y, z, x * x + y * y + z * z);
    }
    __syncthreads();

    const int q = blockIdx.y * 256 + tid;
    const float* q3 = xyz1 + ((size_t)b * NQ + q) * 3;
    const float qx = q3[0], qy = q3[1], qz = q3[2];
    const float mx = -2.f * qx, my = -2.f * qy, mz = -2.f * qz;

    float d0 = 3.4e38f, d1 = 3.4e38f, d2 = 3.4e38f;
    int i0 = 0, i1 = 0, i2 = 0;
#pragma unroll 4
    for (int s = 0; s < SS; s++) {
        float4 c = cand[s];
        float d = fmaf(mx, c.x, fmaf(my, c.y, fmaf(mz, c.z, c.w)));
        if (d < d2) {
            if (d < d1) {
                d2 = d1; i2 = i1;
                if (d < d0) { d1 = d0; i1 = i0; d0 = d; i0 = s; }
                else        { d1 = d;  i1 = s; }
            } else { d2 = d; i2 = s; }
        }
    }
    const float q2 = qx * qx + qy * qy + qz * qz;
    float t0 = sqrtf(fmaxf(d0 + q2, 0.f));
    float t1 = sqrtf(fmaxf(d1 + q2, 0.f));
    float t2 = sqrtf(fmaxf(d2 + q2, 0.f));
    float w0 = 1.f / fmaxf(t0, 1e-10f);
    float w1 = 1.f / fmaxf(t1, 1e-10f);
    float w2 = 1.f / fmaxf(t2, 1e-10f);
    float inv = 1.f / (w0 + w1 + w2);
    const int gbase = b * SS;   // global indices into g_Z row space
    g_idx[(size_t)b * NQ + q] = make_int4(gbase + i0, gbase + i1, gbase + i2, 0);
    g_wt[(size_t)b * NQ + q]  = make_float4(w0 * inv, w1 * inv, w2 * inv, 0.f);
}

// ---------------------------------------------------------------------------
// Pipelined HMMA GEMM, 512 threads, tile 128 x (64*NT), K-chunk 64, 2-stage smem
//   MODE 0: A=points2 fp32 (K=256), B=w1b, NT=2 (grid.y=2)   -> g_Z fp32
//   MODE 1: A=points1 fp32 (K=128), B=w1a, NT=4, epilogue: gather+bn1+relu
//           -> g_h1h/g_h1l (tiled bf16, staged through smem)
//   MODE 2: A=g_h1 tiles  (K=256), B=w2,  NT=4, epilogue bn2+relu -> out
// ---------------------------------------------------------------------------
template <int MODE>
__global__ __launch_bounds__(512, 1) void mma_gemm(const float* __restrict__ Ain,
                                                   float* __restrict__ outp) {
    extern __shared__ char smem[];
    const uint32_t sb = smem_u32(smem);

    constexpr int KK  = (MODE == 1) ? 128 : 256;
    constexpr int NCH = KK / 64;
    constexpr int NT  = (MODE == 0) ? 2 : 4;
    constexpr int BBYTES = 64 * NT * 128;              // B tile bytes (16/32 KB)
    constexpr int ABYTES = 16384;
    constexpr int STAGE  = 2 * ABYTES + 2 * BBYTES;    // 64KB / 96KB
    // stage layout: A_h 0, A_l ABYTES, B_h 2*ABYTES, B_l 2*ABYTES+BBYTES

    const int tid = threadIdx.x, wid = tid >> 5, lane = tid & 31;
    const int row0 = blockIdx.x * 128;
    const int col0 = (MODE == 0) ? blockIdx.y * 128 : 0;
    const int wm = wid & 1, wn = wid >> 1;             // warp tile rows wm*64, cols wn*(8*NT)

    const __nv_bfloat16* BH = (MODE == 0) ? g_w1b_h : (MODE == 1) ? g_w1a_h : g_w2_h;
    const __nv_bfloat16* BL = (MODE == 0) ? g_w1b_l : (MODE == 1) ? g_w1a_l : g_w2_l;

    float acc[4][NT][4];
#pragma unroll
    for (int mt = 0; mt < 4; mt++)
#pragma unroll
        for (int nt = 0; nt < NT; nt++)
#pragma unroll
            for (int e = 0; e < 4; e++) acc[mt][nt][e] = 0.f;

    // ldmatrix per-lane bases
    const int j = lane >> 3, jlo = j & 1, jhi = j >> 1;
    const uint32_t xr = (uint32_t)(lane & 7) << 4;
    const uint32_t aRow = (uint32_t)(wm * 64 + jlo * 8 + (lane & 7)) * 128u;
    const uint32_t bRow = (uint32_t)(wn * (8 * NT) + jlo * 8 + (lane & 7)) * 128u;

    // ---- loaders ----
    auto load_B = [&](int c, int st) {
        const char* srcH = (const char*)BH + c * 32768 + col0 * 128;
        const char* srcL = (const char*)BL + c * 32768 + col0 * 128;
        const uint32_t dH = sb + st * STAGE + 2 * ABYTES;
        const uint32_t dL = dH + BBYTES;
#pragma unroll
        for (int p = 0; p < BBYTES / 16 / 512; p++) {
            int seg = p * 512 + tid;
            cp16(dH + seg * 16, srcH + seg * 16);
            cp16(dL + seg * 16, srcL + seg * 16);
        }
    };
    auto load_A_cp = [&](int c, int st) {   // MODE 2: tiled bf16 identity copy
        const char* srcH = (const char*)g_h1h + (size_t)blockIdx.x * 65536 + c * 16384;
        const char* srcL = (const char*)g_h1l + (size_t)blockIdx.x * 65536 + c * 16384;
        const uint32_t dH = sb + st * STAGE;
        const uint32_t dL = dH + ABYTES;
#pragma unroll
        for (int p = 0; p < 2; p++) {
            int seg = p * 512 + tid;
            cp16(dH + seg * 16, srcH + seg * 16);
            cp16(dL + seg * 16, srcL + seg * 16);
        }
    };
    auto load_A_f32 = [&](int c, int st) {  // MODE 0/1: fp32 load + split + swizzled store
        const int row = tid >> 2, sg = tid & 3;
        const float* ap = Ain + (size_t)(row0 + row) * KK + c * 64 + sg * 16;
        float4 a0 = *(const float4*)(ap + 0);
        float4 a1 = *(const float4*)(ap + 4);
        float4 a2 = *(const float4*)(ap + 8);
        float4 a3 = *(const float4*)(ap + 12);
        uint32_t h[8], l[8];
        split4(a0, h + 0, l + 0); split4(a1, h + 2, l + 2);
        split4(a2, h + 4, l + 4); split4(a3, h + 6, l + 6);
        const uint32_t so0 = sw((uint32_t)row, (uint32_t)sg * 32u);
        const uint32_t so1 = sw((uint32_t)row, (uint32_t)sg * 32u + 16u);
        char* bh_ = smem + st * STAGE;
        *(uint4*)(bh_ + so0)          = make_uint4(h[0], h[1], h[2], h[3]);
        *(uint4*)(bh_ + so1)          = make_uint4(h[4], h[5], h[6], h[7]);
        *(uint4*)(bh_ + ABYTES + so0) = make_uint4(l[0], l[1], l[2], l[3]);
        *(uint4*)(bh_ + ABYTES + so1) = make_uint4(l[4], l[5], l[6], l[7]);
    };
    auto compute = [&](int st) {
        const uint32_t sA_h = sb + st * STAGE;
        const uint32_t sA_l = sA_h + ABYTES;
        const uint32_t sB_h = sA_h + 2 * ABYTES;
        const uint32_t sB_l = sB_h + BBYTES;
#pragma unroll
        for (int ks = 0; ks < 4; ks++) {
            const uint32_t kb = ((uint32_t)(ks * 32 + jhi * 16)) ^ xr;
            uint32_t ah[4][4], bh[NT][2], bl[NT][2];
#pragma unroll
            for (int mt = 0; mt < 4; mt++)
                ldm4(ah[mt], sA_h + aRow + mt * 2048u + kb);
#pragma unroll
            for (int p = 0; p < NT / 2; p++) {
                uint32_t r[4];
                ldm4(r, sB_h + bRow + p * 2048u + kb);
                bh[p * 2 + 0][0] = r[0]; bh[p * 2 + 0][1] = r[2];
                bh[p * 2 + 1][0] = r[1]; bh[p * 2 + 1][1] = r[3];
                ldm4(r, sB_l + bRow + p * 2048u + kb);
                bl[p * 2 + 0][0] = r[0]; bl[p * 2 + 0][1] = r[2];
                bl[p * 2 + 1][0] = r[1]; bl[p * 2 + 1][1] = r[3];
            }
#pragma unroll
            for (int mt = 0; mt < 4; mt++)
#pragma unroll
                for (int nt = 0; nt < NT; nt++) {
                    mma16816(acc[mt][nt], ah[mt], bh[nt]);
                    mma16816(acc[mt][nt], ah[mt], bl[nt]);
                }
            uint32_t al[4][4];
#pragma unroll
            for (int mt = 0; mt < 4; mt++)
                ldm4(al[mt], sA_l + aRow + mt * 2048u + kb);
#pragma unroll
            for (int mt = 0; mt < 4; mt++)
#pragma unroll
                for (int nt = 0; nt < NT; nt++)
                    mma16816(acc[mt][nt], al[mt], bh[nt]);
        }
    };

    // ---- pipelined mainloop ----
    load_B(0, 0);
    if (MODE == 2) load_A_cp(0, 0); else load_A_f32(0, 0);
    CP_COMMIT();
    CP_WAIT();
    __syncthreads();
    for (int c = 0; c < NCH; c++) {
        const int buf = c & 1;
        if (c + 1 < NCH) {
            load_B(c + 1, buf ^ 1);
            if (MODE == 2) load_A_cp(c + 1, buf ^ 1);
            CP_COMMIT();
            if (MODE != 2) load_A_f32(c + 1, buf ^ 1);
        }
        compute(buf);
        if (c + 1 < NCH) CP_WAIT();
        __syncthreads();
    }

    // ---- epilogue ----
    const int g = lane >> 2, t = lane & 3;
    if (MODE == 0) {
#pragma unroll
        for (int mt = 0; mt < 4; mt++) {
            const int ra = row0 + wm * 64 + mt * 16 + g, rb = ra + 8;
#pragma unroll
            for (int nt = 0; nt < NT; nt++) {
                const int col = col0 + wn * (8 * NT) + nt * 8 + 2 * t;
                *(float2*)(g_Z + (size_t)ra * HH + col) = make_float2(acc[mt][nt][0], acc[mt][nt][1]);
                *(float2*)(g_Z + (size_t)rb * HH + col) = make_float2(acc[mt][nt][2], acc[mt][nt][3]);
            }
        }
    } else if (MODE == 2) {
#pragma unroll
        for (int mt = 0; mt < 4; mt++) {
            const int ra = row0 + wm * 64 + mt * 16 + g, rb = ra + 8;
#pragma unroll
            for (int nt = 0; nt < NT; nt++) {
                const int col = wn * (8 * NT) + nt * 8 + 2 * t;
                float sc0 = g_s2[col], sc1 = g_s2[col + 1];
                float bb0 = g_b2[col], bb1 = g_b2[col + 1];
                float v0 = fmaxf(fmaf(acc[mt][nt][0], sc0, bb0), 0.f);
                float v1 = fmaxf(fmaf(acc[mt][nt][1], sc1, bb1), 0.f);
                float v2 = fmaxf(fmaf(acc[mt][nt][2], sc0, bb0), 0.f);
                float v3 = fmaxf(fmaf(acc[mt][nt][3], sc1, bb1), 0.f);
                *(float2*)(outp + (size_t)ra * HH + col) = make_float2(v0, v1);
                *(float2*)(outp + (size_t)rb * HH + col) = make_float2(v2, v3);
            }
        }
    } else {
        // MODE 1: gather pre from Z via idx/w, bn1+relu, split, stage in smem, copy out
#pragma unroll
        for (int mt = 0; mt < 4; mt++) {
            const int rla = wm * 64 + mt * 16 + g, rlb = rla + 8;
            const int ra = row0 + rla, rb = row0 + rlb;
            const int4   ia = g_idx[ra], ib = g_idx[rb];
            const float4 wa = g_wt[ra],  wb = g_wt[rb];
#pragma unroll
            for (int nt = 0; nt < NT; nt++) {
                const int col = wn * (8 * NT) + nt * 8 + 2 * t;
                float2 za0 = *(const float2*)(g_Z + (size_t)ia.x * HH + col);
                float2 za1 = *(const float2*)(g_Z + (size_t)ia.y * HH + col);
                float2 za2 = *(const float2*)(g_Z + (size_t)ia.z * HH + col);
                float2 zb0 = *(const float2*)(g_Z + (size_t)ib.x * HH + col);
                float2 zb1 = *(const float2*)(g_Z + (size_t)ib.y * HH + col);
                float2 zb2 = *(const float2*)(g_Z + (size_t)ib.z * HH + col);
                float p0 = fmaf(wa.x, za0.x, fmaf(wa.y, za1.x, wa.z * za2.x));
                float p1 = fmaf(wa.x, za0.y, fmaf(wa.y, za1.y, wa.z * za2.y));
                float p2 = fmaf(wb.x, zb0.x, fmaf(wb.y, zb1.x, wb.z * zb2.x));
                float p3 = fmaf(wb.x, zb0.y, fmaf(wb.y, zb1.y, wb.z * zb2.y));
                float sc0 = g_s1[col], sc1 = g_s1[col + 1];
                float bb0 = g_b1[col], bb1 = g_b1[col + 1];
                float v0 = fmaxf(fmaf(acc[mt][nt][0] + p0, sc0, bb0), 0.f);
                float v1 = fmaxf(fmaf(acc[mt][nt][1] + p1, sc1, bb1), 0.f);
                float v2 = fmaxf(fmaf(acc[mt][nt][2] + p2, sc0, bb0), 0.f);
                float v3 = fmaxf(fmaf(acc[mt][nt][3] + p3, sc1, bb1), 0.f);
                __nv_bfloat16 h0 = __float2bfloat16_rn(v0), h1 = __float2bfloat16_rn(v1);
                __nv_bfloat16 h2 = __float2bfloat16_rn(v2), h3 = __float2bfloat16_rn(v3);
                __nv_bfloat16 l0 = __float2bfloat16_rn(v0 - __bfloat162float(h0));
                __nv_bfloat16 l1 = __float2bfloat16_rn(v1 - __bfloat162float(h1));
                __nv_bfloat16 l2 = __float2bfloat16_rn(v2 - __bfloat162float(h2));
                __nv_bfloat16 l3 = __float2bfloat16_rn(v3 - __bfloat162float(h3));
                // smem staging: hi at [chunk][row][swz], lo at +65536
                const int chunk = col >> 6, kin = col & 63;
                const uint32_t offa = chunk * 16384 + (uint32_t)rla * 128 + (((uint32_t)kin * 2) ^ (((uint32_t)rla & 7) << 4));
                const uint32_t offb = chunk * 16384 + (uint32_t)rlb * 128 + (((uint32_t)kin * 2) ^ (((uint32_t)rlb & 7) << 4));
                *(uint32_t*)(smem + offa)         = pack2(h0, h1);
                *(uint32_t*)(smem + 65536 + offa) = pack2(l0, l1);
                *(uint32_t*)(smem + offb)         = pack2(h2, h3);
                *(uint32_t*)(smem + 65536 + offb) = pack2(l2, l3);
            }
        }
        __syncthreads();
        // coalesced copy of staged tiles to global (identity layout)
        char* dH = (char*)g_h1h + (size_t)blockIdx.x * 65536;
        char* dL = (char*)g_h1l + (size_t)blockIdx.x * 65536;
#pragma unroll
        for (int p = 0; p < 8; p++) {
            int seg = p * 512 + tid;     // 4096 segs x 16B = 64KB
            *(uint4*)(dH + seg * 16) = *(const uint4*)(smem + seg * 16);
            *(uint4*)(dL + seg * 16) = *(const uint4*)(smem + 65536 + seg * 16);
        }
    }
}

// ---------------------------------------------------------------------------
// Launch
// ---------------------------------------------------------------------------
extern "C" void kernel_launch(void* const* d_in, const int* in_sizes, int n_in,
                              void* d_out, int out_size) {
    const float* xyz1    = (const float*)d_in[0];
    const float* xyz2    = (const float*)d_in[1];
    const float* points1 = (const float*)d_in[2];
    const float* points2 = (const float*)d_in[3];
    const float* W1      = (const float*)d_in[4];
    const float* gamma1  = (const float*)d_in[5];
    const float* beta1   = (const float*)d_in[6];
    const float* rm1     = (const float*)d_in[7];
    const float* rv1     = (const float*)d_in[8];
    const float* W2      = (const float*)d_in[9];
    const float* gamma2  = (const float*)d_in[10];
    const float* beta2   = (const float*)d_in[11];
    const float* rm2     = (const float*)d_in[12];
    const float* rv2     = (const float*)d_in[13];
    float* out = (float*)d_out;

    cudaFuncSetAttribute(mma_gemm<0>, cudaFuncAttributeMaxDynamicSharedMemorySize, 131072);
    cudaFuncSetAttribute(mma_gemm<1>, cudaFuncAttributeMaxDynamicSharedMemorySize, 196608);
    cudaFuncSetAttribute(mma_gemm<2>, cudaFuncAttributeMaxDynamicSharedMemorySize, 196608);

    bn_prep<<<1, HH>>>(gamma1, beta1, rm1, rv1, gamma2, beta2, rm2, rv2);
    split_weights<<<640, 256>>>(W1, W2);

    // 3-NN indices + weights (global indices)
    nn_idx<<<dim3(BB, NQ / 256), 256>>>(xyz1, xyz2);

    // Z = points2 @ W1b^T
    mma_gemm<0><<<dim3(SROWS / 128, 2), 512, 131072>>>(points2, nullptr);

    // h1 = relu(bn1(points1 @ W1a^T + gather(Z)))  -> tiled bf16 hi/lo
    mma_gemm<1><<<dim3(MROWS / 128, 1), 512, 196608>>>(points1, nullptr);

    // out = relu(bn2(h1 @ W2^T))
    mma_gemm<2><<<dim3(MROWS / 128, 1), 512, 196608>>>(nullptr, out);
}

// round 8
// speedup vs baseline: 1.7311x; 1.0409x over previous
#include <cuda_runtime.h>
#include <cuda_bf16.h>
#include <cstdint>

// Problem constants
#define BB 4
#define NQ 16384
#define SS 2048
#define C1 128
#define C2 256
#define HH 256
#define MROWS (BB * NQ)   // 65536
#define SROWS (BB * SS)   // 8192

// ---------------------------------------------------------------------------
// Device scratch
// ---------------------------------------------------------------------------
__device__ float g_Z[SROWS * HH];                       // 8MB, L2-resident
__device__ __nv_bfloat16 g_h1h[(size_t)MROWS * HH];     // h1 hi, tiled+swizzled
__device__ __nv_bfloat16 g_h1l[(size_t)MROWS * HH];     // h1 lo, tiled+swizzled
__device__ int4   g_idx[MROWS];                         // 3-NN indices (GLOBAL: b*SS+s)
__device__ float4 g_wt[MROWS];                          // 3-NN weights (normalized)
// weights pre-split, tiled+swizzled: [chunk][n 256 rows][64 k, SW128]
__device__ __nv_bfloat16 g_w1a_h[HH * C1], g_w1a_l[HH * C1];
__device__ __nv_bfloat16 g_w1b_h[HH * C2], g_w1b_l[HH * C2];
__device__ __nv_bfloat16 g_w2_h[HH * HH],  g_w2_l[HH * HH];
__device__ float g_s1[HH], g_b1[HH], g_s2[HH], g_b2[HH];

// ---------------------------------------------------------------------------
// Helpers
// ---------------------------------------------------------------------------
__device__ __forceinline__ uint32_t smem_u32(const void* p) {
    uint32_t a;
    asm("{ .reg .u64 t; cvta.to.shared.u64 t, %1; cvt.u32.u64 %0, t; }" : "=r"(a) : "l"(p));
    return a;
}
__device__ __forceinline__ void ldm4(uint32_t* r, uint32_t addr) {
    asm volatile("ldmatrix.sync.aligned.m8n8.x4.shared.b16 {%0,%1,%2,%3}, [%4];"
                 : "=r"(r[0]), "=r"(r[1]), "=r"(r[2]), "=r"(r[3]) : "r"(addr));
}
__device__ __forceinline__ void mma16816(float* c, const uint32_t* a, const uint32_t* b) {
    asm volatile(
        "mma.sync.aligned.m16n8k16.row.col.f32.bf16.bf16.f32 "
        "{%0,%1,%2,%3}, {%4,%5,%6,%7}, {%8,%9}, {%0,%1,%2,%3};"
        : "+f"(c[0]), "+f"(c[1]), "+f"(c[2]), "+f"(c[3])
        : "r"(a[0]), "r"(a[1]), "r"(a[2]), "r"(a[3]), "r"(b[0]), "r"(b[1]));
}
__device__ __forceinline__ void cp16(uint32_t dst, const void* src) {
    asm volatile("cp.async.cg.shared.global [%0], [%1], 16;" :: "r"(dst), "l"(src));
}
#define CP_COMMIT() asm volatile("cp.async.commit_group;" ::: "memory")
#define CP_WAIT()   asm volatile("cp.async.wait_group 0;" ::: "memory")

__device__ __forceinline__ uint32_t pack2(__nv_bfloat16 a, __nv_bfloat16 b) {
    return (uint32_t)__bfloat16_as_ushort(a) | ((uint32_t)__bfloat16_as_ushort(b) << 16);
}
__device__ __forceinline__ void split4(float4 v, uint32_t* hi, uint32_t* lo) {
    __nv_bfloat16 h0 = __float2bfloat16_rn(v.x);
    __nv_bfloat16 h1 = __float2bfloat16_rn(v.y);
    __nv_bfloat16 h2 = __float2bfloat16_rn(v.z);
    __nv_bfloat16 h3 = __float2bfloat16_rn(v.w);
    __nv_bfloat16 l0 = __float2bfloat16_rn(v.x - __bfloat162float(h0));
    __nv_bfloat16 l1 = __float2bfloat16_rn(v.y - __bfloat162float(h1));
    __nv_bfloat16 l2 = __float2bfloat16_rn(v.z - __bfloat162float(h2));
    __nv_bfloat16 l3 = __float2bfloat16_rn(v.w - __bfloat162float(h3));
    hi[0] = pack2(h0, h1); hi[1] = pack2(h2, h3);
    lo[0] = pack2(l0, l1); lo[1] = pack2(l2, l3);
}
__device__ __forceinline__ uint32_t sw(uint32_t row, uint32_t kb) {
    return row * 128u + (kb ^ ((row & 7u) << 4));
}

// ---------------------------------------------------------------------------
// BN fold
// ---------------------------------------------------------------------------
__global__ void bn_prep(const float* __restrict__ g1, const float* __restrict__ be1,
                        const float* __restrict__ rm1, const float* __restrict__ rv1,
                        const float* __restrict__ g2, const float* __restrict__ be2,
                        const float* __restrict__ rm2, const float* __restrict__ rv2) {
    int h = threadIdx.x;
    float s1 = g1[h] * rsqrtf(rv1[h] + 1e-5f);
    g_s1[h] = s1; g_b1[h] = be1[h] - rm1[h] * s1;
    float s2 = g2[h] * rsqrtf(rv2[h] + 1e-5f);
    g_s2[h] = s2; g_b2[h] = be2[h] - rm2[h] * s2;
}

// ---------------------------------------------------------------------------
// Weight split into tiled+swizzled bf16 hi/lo
// ---------------------------------------------------------------------------
__global__ __launch_bounds__(256) void split_weights(const float* __restrict__ W1,
                                                     const float* __restrict__ W2) {
    int i = blockIdx.x * 256 + threadIdx.x;   // 163840 total
    float v; __nv_bfloat16 *H, *L; int n, k;
    if (i < 32768)       { n = i >> 7; k = i & 127; v = W1[n * 384 + k];       H = g_w1a_h; L = g_w1a_l; }
    else if (i < 98304)  { int j = i - 32768; n = j >> 8; k = j & 255; v = W1[n * 384 + 128 + k]; H = g_w1b_h; L = g_w1b_l; }
    else                 { int j = i - 98304; n = j >> 8; k = j & 255; v = W2[n * 256 + k];       H = g_w2_h;  L = g_w2_l; }
    __nv_bfloat16 h = __float2bfloat16_rn(v);
    __nv_bfloat16 l = __float2bfloat16_rn(v - __bfloat162float(h));
    int chunk = k >> 6, kin = k & 63;
    int boff = n * 128 + ((kin * 2) ^ ((n & 7) << 4));
    int off = chunk * 16384 + (boff >> 1);
    H[off] = h; L[off] = l;
}

// ---------------------------------------------------------------------------
// 3-NN search: writes GLOBAL idx (b*SS + s) + normalized weights
// ---------------------------------------------------------------------------
__global__ __launch_bounds__(256) void nn_idx(const float* __restrict__ xyz1,
                                              const float* __restrict__ xyz2) {
    __shared__ __align__(16) float4 cand[SS];
    const int b = blockIdx.x, tid = threadIdx.x;
    const float* x2 = xyz2 + (size_t)b * SS * 3;
    for (int s = tid; s < SS; s += 256) {
        float x = x2[s * 3 + 0], y = x2[s * 3 + 1], z = x2[s * 3 + 2];
        cand[s] = make_float4(x, y, z, x * x + y * y + z * z);
    }
    __syncthreads();

    const int q = blockIdx.y * 256 + tid;
    const float* q3 = xyz1 + ((size_t)b * NQ + q) * 3;
    const float qx = q3[0], qy = q3[1], qz = q3[2];
    const float mx = -2.f * qx, my = -2.f * qy, mz = -2.f * qz;

    float d0 = 3.4e38f, d1 = 3.4e38f, d2 = 3.4e38f;
    int i0 = 0, i1 = 0, i2 = 0;
#pragma unroll 4
    for (int s = 0; s < SS; s++) {
        float4 c = cand[s];
        float d = fmaf(mx, c.x, fmaf(my, c.y, fmaf(mz, c.z, c.w)));
        if (d < d2) {
            if (d < d1) {
                d2 = d1; i2 = i1;
                if (d < d0) { d1 = d0; i1 = i0; d0 = d; i0 = s; }
                else        { d1 = d;  i1 = s; }
            } else { d2 = d; i2 = s; }
        }
    }
    const float q2 = qx * qx + qy * qy + qz * qz;
    float t0 = sqrtf(fmaxf(d0 + q2, 0.f));
    float t1 = sqrtf(fmaxf(d1 + q2, 0.f));
    float t2 = sqrtf(fmaxf(d2 + q2, 0.f));
    float w0 = 1.f / fmaxf(t0, 1e-10f);
    float w1 = 1.f / fmaxf(t1, 1e-10f);
    float w2 = 1.f / fmaxf(t2, 1e-10f);
    float inv = 1.f / (w0 + w1 + w2);
    const int gbase = b * SS;
    g_idx[(size_t)b * NQ + q] = make_int4(gbase + i0, gbase + i1, gbase + i2, 0);
    g_wt[(size_t)b * NQ + q]  = make_float4(w0 * inv, w1 * inv, w2 * inv, 0.f);
}

// ---------------------------------------------------------------------------
// Pipelined HMMA GEMM. 512 threads = 16 warps, warp tile 32x32 (acc 32 regs).
// CTA tile 128(M) x 128(N), N split via grid.y=2. K-chunk 64, double-buffered
// cp.async stages + k-step fragment double-buffering + LDG/compute overlap.
//   MODE 0: A=points2 fp32 (K=256), B=w1b -> g_Z fp32
//   MODE 1: A=points1 fp32 (K=128), B=w1a, epi: gather(Z)+bn1+relu -> h1 bf16 hi/lo
//   MODE 2: A=g_h1 bf16 tiles (K=256), B=w2, epi: bn2+relu -> out
// ---------------------------------------------------------------------------
#define ABYTES 16384
#define BBYTES 16384
#define STAGE  (2 * ABYTES + 2 * BBYTES)   // 64KB: A_h, A_l, B_h, B_l
#define SMEM_SZ (2 * STAGE)                // 128KB

template <int MODE>
__global__ __launch_bounds__(512, 1) void mma_gemm(const float* __restrict__ Ain,
                                                   float* __restrict__ outp) {
    extern __shared__ char smem[];
    const uint32_t sb = smem_u32(smem);

    constexpr int KK  = (MODE == 1) ? 128 : 256;
    constexpr int NCH = KK / 64;

    const int tid = threadIdx.x, wid = tid >> 5, lane = tid & 31;
    const int row0 = blockIdx.x * 128;
    const int col0 = blockIdx.y * 128;
    const int wm = wid & 3, wn = wid >> 2;   // warp tile rows wm*32, cols wn*32

    const __nv_bfloat16* BH = (MODE == 0) ? g_w1b_h : (MODE == 1) ? g_w1a_h : g_w2_h;
    const __nv_bfloat16* BL = (MODE == 0) ? g_w1b_l : (MODE == 1) ? g_w1a_l : g_w2_l;

    float acc[2][4][4];
#pragma unroll
    for (int mt = 0; mt < 2; mt++)
#pragma unroll
        for (int nt = 0; nt < 4; nt++)
#pragma unroll
            for (int e = 0; e < 4; e++) acc[mt][nt][e] = 0.f;

    // ldmatrix per-lane bases
    const int j = lane >> 3, jlo = j & 1, jhi = j >> 1;
    const uint32_t xr = (uint32_t)(lane & 7) << 4;
    const uint32_t aRow = (uint32_t)(wm * 32 + jlo * 8 + (lane & 7)) * 128u;
    const uint32_t bRow = (uint32_t)(wn * 32 + jlo * 8 + (lane & 7)) * 128u;

    // A fp32 prefetch registers (one 16-float segment per thread)
    const int arow = tid >> 2, asg = tid & 3;
    float4 aNext[4];

    // ---- loaders ----
    auto load_B = [&](int c, int st) {
        const char* srcH = (const char*)BH + c * 32768 + col0 * 128;
        const char* srcL = (const char*)BL + c * 32768 + col0 * 128;
        const uint32_t dH = sb + st * STAGE + 2 * ABYTES;
        const uint32_t dL = dH + BBYTES;
#pragma unroll
        for (int p = 0; p < 2; p++) {
            int seg = p * 512 + tid;       // 1024 segs x 16B = 16KB each
            cp16(dH + seg * 16, srcH + seg * 16);
            cp16(dL + seg * 16, srcL + seg * 16);
        }
    };
    auto load_A_cp = [&](int c, int st) {  // MODE 2: tiled bf16 identity copy
        const char* srcH = (const char*)g_h1h + (size_t)blockIdx.x * 65536 + c * 16384;
        const char* srcL = (const char*)g_h1l + (size_t)blockIdx.x * 65536 + c * 16384;
        const uint32_t dH = sb + st * STAGE;
        const uint32_t dL = dH + ABYTES;
#pragma unroll
        for (int p = 0; p < 2; p++) {
            int seg = p * 512 + tid;
            cp16(dH + seg * 16, srcH + seg * 16);
            cp16(dL + seg * 16, srcL + seg * 16);
        }
    };
    auto lda_issue = [&](int c) {          // MODE 0/1: fp32 LDG into regs
        const float* ap = Ain + (size_t)(row0 + arow) * KK + c * 64 + asg * 16;
        aNext[0] = *(const float4*)(ap + 0);
        aNext[1] = *(const float4*)(ap + 4);
        aNext[2] = *(const float4*)(ap + 8);
        aNext[3] = *(const float4*)(ap + 12);
    };
    auto lda_store = [&](int st) {         // split + swizzled STS
        uint32_t h[8], l[8];
        split4(aNext[0], h + 0, l + 0); split4(aNext[1], h + 2, l + 2);
        split4(aNext[2], h + 4, l + 4); split4(aNext[3], h + 6, l + 6);
        const uint32_t so0 = sw((uint32_t)arow, (uint32_t)asg * 32u);
        const uint32_t so1 = sw((uint32_t)arow, (uint32_t)asg * 32u + 16u);
        char* bp = smem + st * STAGE;
        *(uint4*)(bp + so0)          = make_uint4(h[0], h[1], h[2], h[3]);
        *(uint4*)(bp + so1)          = make_uint4(h[4], h[5], h[6], h[7]);
        *(uint4*)(bp + ABYTES + so0) = make_uint4(l[0], l[1], l[2], l[3]);
        *(uint4*)(bp + ABYTES + so1) = make_uint4(l[4], l[5], l[6], l[7]);
    };

    auto ldfrag = [&](uint32_t base, int ks, uint32_t (*ah)[4], uint32_t (*al)[4],
                      uint32_t (*bh)[2], uint32_t (*bl)[2]) {
        const uint32_t kb = ((uint32_t)(ks * 32 + jhi * 16)) ^ xr;
        const uint32_t sA_h = base, sA_l = base + ABYTES;
        const uint32_t sB_h = base + 2 * ABYTES, sB_l = sB_h + BBYTES;
        ldm4(ah[0], sA_h + aRow + kb);
        ldm4(ah[1], sA_h + aRow + 2048u + kb);
        ldm4(al[0], sA_l + aRow + kb);
        ldm4(al[1], sA_l + aRow + 2048u + kb);
#pragma unroll
        for (int p = 0; p < 2; p++) {
            uint32_t r[4];
            ldm4(r, sB_h + bRow + p * 2048u + kb);
            bh[p * 2 + 0][0] = r[0]; bh[p * 2 + 0][1] = r[2];
            bh[p * 2 + 1][0] = r[1]; bh[p * 2 + 1][1] = r[3];
            ldm4(r, sB_l + bRow + p * 2048u + kb);
            bl[p * 2 + 0][0] = r[0]; bl[p * 2 + 0][1] = r[2];
            bl[p * 2 + 1][0] = r[1]; bl[p * 2 + 1][1] = r[3];
        }
    };

    auto compute = [&](int bufsel) {
        const uint32_t base = sb + bufsel * STAGE;
        uint32_t ahf[2][2][4], alf[2][2][4], bhf[2][4][2], blf[2][4][2];
        ldfrag(base, 0, ahf[0], alf[0], bhf[0], blf[0]);
#pragma unroll
        for (int ks = 0; ks < 4; ks++) {
            const int cur = ks & 1, nxt = cur ^ 1;
            if (ks < 3) ldfrag(base, ks + 1, ahf[nxt], alf[nxt], bhf[nxt], blf[nxt]);
#pragma unroll
            for (int mt = 0; mt < 2; mt++)
#pragma unroll
                for (int nt = 0; nt < 4; nt++)
                    mma16816(acc[mt][nt], ahf[cur][mt], bhf[cur][nt]);
#pragma unroll
            for (int mt = 0; mt < 2; mt++)
#pragma unroll
                for (int nt = 0; nt < 4; nt++)
                    mma16816(acc[mt][nt], ahf[cur][mt], blf[cur][nt]);
#pragma unroll
            for (int mt = 0; mt < 2; mt++)
#pragma unroll
                for (int nt = 0; nt < 4; nt++)
                    mma16816(acc[mt][nt], alf[cur][mt], bhf[cur][nt]);
        }
    };

    // ---- pipelined mainloop ----
    load_B(0, 0);
    if (MODE == 2) load_A_cp(0, 0);
    CP_COMMIT();
    if (MODE != 2) { lda_issue(0); lda_store(0); }
    CP_WAIT();
    __syncthreads();
    for (int c = 0; c < NCH; c++) {
        const int buf = c & 1;
        if (c + 1 < NCH) {
            load_B(c + 1, buf ^ 1);
            if (MODE == 2) load_A_cp(c + 1, buf ^ 1);
            CP_COMMIT();
            if (MODE != 2) lda_issue(c + 1);
        }
        compute(buf);
        if (c + 1 < NCH) {
            if (MODE != 2) lda_store(buf ^ 1);
            CP_WAIT();
        }
        __syncthreads();
    }

    // ---- epilogue ----
    const int g = lane >> 2, t = lane & 3;
    if (MODE == 0) {
#pragma unroll
        for (int mt = 0; mt < 2; mt++) {
            const int ra = row0 + wm * 32 + mt * 16 + g, rb = ra + 8;
#pragma unroll
            for (int nt = 0; nt < 4; nt++) {
                const int col = col0 + wn * 32 + nt * 8 + 2 * t;
                *(float2*)(g_Z + (size_t)ra * HH + col) = make_float2(acc[mt][nt][0], acc[mt][nt][1]);
                *(float2*)(g_Z + (size_t)rb * HH + col) = make_float2(acc[mt][nt][2], acc[mt][nt][3]);
            }
        }
    } else if (MODE == 2) {
#pragma unroll
        for (int mt = 0; mt < 2; mt++) {
            const int ra = row0 + wm * 32 + mt * 16 + g, rb = ra + 8;
#pragma unroll
            for (int nt = 0; nt < 4; nt++) {
                const int col = col0 + wn * 32 + nt * 8 + 2 * t;
                float sc0 = g_s2[col], sc1 = g_s2[col + 1];
                float bb0 = g_b2[col], bb1 = g_b2[col + 1];
                float v0 = fmaxf(fmaf(acc[mt][nt][0], sc0, bb0), 0.f);
                float v1 = fmaxf(fmaf(acc[mt][nt][1], sc1, bb1), 0.f);
                float v2 = fmaxf(fmaf(acc[mt][nt][2], sc0, bb0), 0.f);
                float v3 = fmaxf(fmaf(acc[mt][nt][3], sc1, bb1), 0.f);
                *(float2*)(outp + (size_t)ra * HH + col) = make_float2(v0, v1);
                *(float2*)(outp + (size_t)rb * HH + col) = make_float2(v2, v3);
            }
        }
    } else {
        // MODE 1: gather from Z, bn1+relu, split, stage (64KB), copy out
#pragma unroll
        for (int mt = 0; mt < 2; mt++) {
            const int rla = wm * 32 + mt * 16 + g, rlb = rla + 8;
            const int ra = row0 + rla, rb = row0 + rlb;
            const int4   ia = g_idx[ra], ib = g_idx[rb];
            const float4 wa = g_wt[ra],  wb = g_wt[rb];
#pragma unroll
            for (int nt = 0; nt < 4; nt++) {
                const int lcol = wn * 32 + nt * 8 + 2 * t;
                const int col = col0 + lcol;
                float2 za0 = *(const float2*)(g_Z + (size_t)ia.x * HH + col);
                float2 za1 = *(const float2*)(g_Z + (size_t)ia.y * HH + col);
                float2 za2 = *(const float2*)(g_Z + (size_t)ia.z * HH + col);
                float2 zb0 = *(const float2*)(g_Z + (size_t)ib.x * HH + col);
                float2 zb1 = *(const float2*)(g_Z + (size_t)ib.y * HH + col);
                float2 zb2 = *(const float2*)(g_Z + (size_t)ib.z * HH + col);
                float p0 = fmaf(wa.x, za0.x, fmaf(wa.y, za1.x, wa.z * za2.x));
                float p1 = fmaf(wa.x, za0.y, fmaf(wa.y, za1.y, wa.z * za2.y));
                float p2 = fmaf(wb.x, zb0.x, fmaf(wb.y, zb1.x, wb.z * zb2.x));
                float p3 = fmaf(wb.x, zb0.y, fmaf(wb.y, zb1.y, wb.z * zb2.y));
                float sc0 = g_s1[col], sc1 = g_s1[col + 1];
                float bb0 = g_b1[col], bb1 = g_b1[col + 1];
                float v0 = fmaxf(fmaf(acc[mt][nt][0] + p0, sc0, bb0), 0.f);
                float v1 = fmaxf(fmaf(acc[mt][nt][1] + p1, sc1, bb1), 0.f);
                float v2 = fmaxf(fmaf(acc[mt][nt][2] + p2, sc0, bb0), 0.f);
                float v3 = fmaxf(fmaf(acc[mt][nt][3] + p3, sc1, bb1), 0.f);
                __nv_bfloat16 h0 = __float2bfloat16_rn(v0), h1 = __float2bfloat16_rn(v1);
                __nv_bfloat16 h2 = __float2bfloat16_rn(v2), h3 = __float2bfloat16_rn(v3);
                __nv_bfloat16 l0 = __float2bfloat16_rn(v0 - __bfloat162float(h0));
                __nv_bfloat16 l1 = __float2bfloat16_rn(v1 - __bfloat162float(h1));
                __nv_bfloat16 l2 = __float2bfloat16_rn(v2 - __bfloat162float(h2));
                __nv_bfloat16 l3 = __float2bfloat16_rn(v3 - __bfloat162float(h3));
                const int lc = lcol >> 6, kin = lcol & 63;
                const uint32_t offa = lc * 16384 + (uint32_t)rla * 128 + (((uint32_t)kin * 2) ^ (((uint32_t)rla & 7) << 4));
                const uint32_t offb = lc * 16384 + (uint32_t)rlb * 128 + (((uint32_t)kin * 2) ^ (((uint32_t)rlb & 7) << 4));
                *(uint32_t*)(smem + offa)         = pack2(h0, h1);
                *(uint32_t*)(smem + 32768 + offa) = pack2(l0, l1);
                *(uint32_t*)(smem + offb)         = pack2(h2, h3);
                *(uint32_t*)(smem + 32768 + offb) = pack2(l2, l3);
            }
        }
        __syncthreads();
        // coalesced copy of staged 2 chunks (32KB hi + 32KB lo) to global
        const uint32_t gcb = (uint32_t)(col0 >> 6) * 16384u;
        char* dH = (char*)g_h1h + (size_t)blockIdx.x * 65536 + gcb;
        char* dL = (char*)g_h1l + (size_t)blockIdx.x * 65536 + gcb;
#pragma unroll
        for (int p = 0; p < 4; p++) {
            int seg = p * 512 + tid;     // 2048 segs x 16B = 32KB
            *(uint4*)(dH + seg * 16) = *(const uint4*)(smem + seg * 16);
            *(uint4*)(dL + seg * 16) = *(const uint4*)(smem + 32768 + seg * 16);
        }
    }
}

// ---------------------------------------------------------------------------
// Launch
// ---------------------------------------------------------------------------
extern "C" void kernel_launch(void* const* d_in, const int* in_sizes, int n_in,
                              void* d_out, int out_size) {
    const float* xyz1    = (const float*)d_in[0];
    const float* xyz2    = (const float*)d_in[1];
    const float* points1 = (const float*)d_in[2];
    const float* points2 = (const float*)d_in[3];
    const float* W1      = (const float*)d_in[4];
    const float* gamma1  = (const float*)d_in[5];
    const float* beta1   = (const float*)d_in[6];
    const float* rm1     = (const float*)d_in[7];
    const float* rv1     = (const float*)d_in[8];
    const float* W2      = (const float*)d_in[9];
    const float* gamma2  = (const float*)d_in[10];
    const float* beta2   = (const float*)d_in[11];
    const float* rm2     = (const float*)d_in[12];
    const float* rv2     = (const float*)d_in[13];
    float* out = (float*)d_out;

    cudaFuncSetAttribute(mma_gemm<0>, cudaFuncAttributeMaxDynamicSharedMemorySize, SMEM_SZ);
    cudaFuncSetAttribute(mma_gemm<1>, cudaFuncAttributeMaxDynamicSharedMemorySize, SMEM_SZ);
    cudaFuncSetAttribute(mma_gemm<2>, cudaFuncAttributeMaxDynamicSharedMemorySize, SMEM_SZ);

    bn_prep<<<1, HH>>>(gamma1, beta1, rm1, rv1, gamma2, beta2, rm2, rv2);
    split_weights<<<640, 256>>>(W1, W2);

    // 3-NN indices + weights (global indices)
    nn_idx<<<dim3(BB, NQ / 256), 256>>>(xyz1, xyz2);

    // Z = points2 @ W1b^T
    mma_gemm<0><<<dim3(SROWS / 128, 2), 512, SMEM_SZ>>>(points2, nullptr);

    // h1 = relu(bn1(points1 @ W1a^T + gather(Z)))  -> tiled bf16 hi/lo
    mma_gemm<1><<<dim3(MROWS / 128, 2), 512, SMEM_SZ>>>(points1, nullptr);

    // out = relu(bn2(h1 @ W2^T))
    mma_gemm<2><<<dim3(MROWS / 128, 2), 512, SMEM_SZ>>>(nullptr, out);
}

// round 11
// speedup vs baseline: 2.2028x; 1.2725x over previous
#include <cuda_runtime.h>
#include <cuda_fp16.h>
#include <cstdint>

// Problem constants
#define BB 4
#define NQ 16384
#define SS 2048
#define C1 128
#define C2 256
#define HH 256
#define MROWS (BB * NQ)   // 65536
#define SROWS (BB * SS)   // 8192

// ---------------------------------------------------------------------------
// Device scratch
// ---------------------------------------------------------------------------
__device__ float g_Z[SROWS * HH];                 // 8MB, L2-resident
__device__ __half g_h1[(size_t)MROWS * HH];       // h1 fp16, tiled+swizzled (32MB)
__device__ int4   g_idx[MROWS];                   // 3-NN indices (GLOBAL: b*SS+s)
__device__ float4 g_wt[MROWS];                    // 3-NN weights (normalized)
// weights fp16 hi/lo split, tiled+swizzled: [chunk][n 256 rows][64 k, SW128]
__device__ __half g_w1a_h[HH * C1], g_w1a_l[HH * C1];
__device__ __half g_w1b_h[HH * C2], g_w1b_l[HH * C2];
__device__ __half g_w2_h[HH * HH],  g_w2_l[HH * HH];
__device__ float g_s1[HH], g_b1[HH], g_s2[HH], g_b2[HH];

// ---------------------------------------------------------------------------
// Helpers
// ---------------------------------------------------------------------------
__device__ __forceinline__ uint32_t smem_u32(const void* p) {
    uint32_t a;
    asm("{ .reg .u64 t; cvta.to.shared.u64 t, %1; cvt.u32.u64 %0, t; }" : "=r"(a) : "l"(p));
    return a;
}
__device__ __forceinline__ void ldm4(uint32_t* r, uint32_t addr) {
    asm volatile("ldmatrix.sync.aligned.m8n8.x4.shared.b16 {%0,%1,%2,%3}, [%4];"
                 : "=r"(r[0]), "=r"(r[1]), "=r"(r[2]), "=r"(r[3]) : "r"(addr));
}
__device__ __forceinline__ void mma16816(float* c, const uint32_t* a, const uint32_t* b) {
    asm volatile(
        "mma.sync.aligned.m16n8k16.row.col.f32.f16.f16.f32 "
        "{%0,%1,%2,%3}, {%4,%5,%6,%7}, {%8,%9}, {%0,%1,%2,%3};"
        : "+f"(c[0]), "+f"(c[1]), "+f"(c[2]), "+f"(c[3])
        : "r"(a[0]), "r"(a[1]), "r"(a[2]), "r"(a[3]), "r"(b[0]), "r"(b[1]));
}
__device__ __forceinline__ void cp16(uint32_t dst, const void* src) {
    asm volatile("cp.async.cg.shared.global [%0], [%1], 16;" :: "r"(dst), "l"(src));
}
#define CP_COMMIT() asm volatile("cp.async.commit_group;" ::: "memory")
#define CP_WAIT()   asm volatile("cp.async.wait_group 0;" ::: "memory")

__device__ __forceinline__ uint32_t packh2(float a, float b) {
    __half2 h = __floats2half2_rn(a, b);
    return *(uint32_t*)&h;
}
__device__ __forceinline__ uint32_t sw(uint32_t row, uint32_t kb) {
    return row * 128u + (kb ^ ((row & 7u) << 4));
}

// ---------------------------------------------------------------------------
// BN fold
// ---------------------------------------------------------------------------
__global__ void bn_prep(const float* __restrict__ g1, const float* __restrict__ be1,
                        const float* __restrict__ rm1, const float* __restrict__ rv1,
                        const float* __restrict__ g2, const float* __restrict__ be2,
                        const float* __restrict__ rm2, const float* __restrict__ rv2) {
    int h = threadIdx.x;
    float s1 = g1[h] * rsqrtf(rv1[h] + 1e-5f);
    g_s1[h] = s1; g_b1[h] = be1[h] - rm1[h] * s1;
    float s2 = g2[h] * rsqrtf(rv2[h] + 1e-5f);
    g_s2[h] = s2; g_b2[h] = be2[h] - rm2[h] * s2;
}

// ---------------------------------------------------------------------------
// Weight split into tiled+swizzled fp16 hi/lo  (w = wh + wl, wl ~ 2^-11 |w|)
// ---------------------------------------------------------------------------
__global__ __launch_bounds__(256) void split_weights(const float* __restrict__ W1,
                                                     const float* __restrict__ W2) {
    int i = blockIdx.x * 256 + threadIdx.x;   // 163840 total
    float v; __half *H, *L; int n, k;
    if (i < 32768)       { n = i >> 7; k = i & 127; v = W1[n * 384 + k];       H = g_w1a_h; L = g_w1a_l; }
    else if (i < 98304)  { int j = i - 32768; n = j >> 8; k = j & 255; v = W1[n * 384 + 128 + k]; H = g_w1b_h; L = g_w1b_l; }
    else                 { int j = i - 98304; n = j >> 8; k = j & 255; v = W2[n * 256 + k];       H = g_w2_h;  L = g_w2_l; }
    __half h = __float2half_rn(v);
    __half l = __float2half_rn(v - __half2float(h));
    int chunk = k >> 6, kin = k & 63;
    int boff = n * 128 + ((kin * 2) ^ ((n & 7) << 4));
    int off = chunk * 16384 + (boff >> 1);
    H[off] = h; L[off] = l;
}

// ---------------------------------------------------------------------------
// 3-NN search: writes GLOBAL idx (b*SS + s) + normalized weights
// ---------------------------------------------------------------------------
__global__ __launch_bounds__(256) void nn_idx(const float* __restrict__ xyz1,
                                              const float* __restrict__ xyz2) {
    __shared__ __align__(16) float4 cand[SS];
    const int b = blockIdx.x, tid = threadIdx.x;
    const float* x2 = xyz2 + (size_t)b * SS * 3;
    for (int s = tid; s < SS; s += 256) {
        float x = x2[s * 3 + 0], y = x2[s * 3 + 1], z = x2[s * 3 + 2];
        cand[s] = make_float4(x, y, z, x * x + y * y + z * z);
    }
    __syncthreads();

    const int q = blockIdx.y * 256 + tid;
    const float* q3 = xyz1 + ((size_t)b * NQ + q) * 3;
    const float qx = q3[0], qy = q3[1], qz = q3[2];
    const float mx = -2.f * qx, my = -2.f * qy, mz = -2.f * qz;

    float d0 = 3.4e38f, d1 = 3.4e38f, d2 = 3.4e38f;
    int i0 = 0, i1 = 0, i2 = 0;
#pragma unroll 4
    for (int s = 0; s < SS; s++) {
        float4 c = cand[s];
        float d = fmaf(mx, c.x, fmaf(my, c.y, fmaf(mz, c.z, c.w)));
        if (d < d2) {
            if (d < d1) {
                d2 = d1; i2 = i1;
                if (d < d0) { d1 = d0; i1 = i0; d0 = d; i0 = s; }
                else        { d1 = d;  i1 = s; }
            } else { d2 = d; i2 = s; }
        }
    }
    const float q2 = qx * qx + qy * qy + qz * qz;
    float t0 = sqrtf(fmaxf(d0 + q2, 0.f));
    float t1 = sqrtf(fmaxf(d1 + q2, 0.f));
    float t2 = sqrtf(fmaxf(d2 + q2, 0.f));
    float w0 = 1.f / fmaxf(t0, 1e-10f);
    float w1 = 1.f / fmaxf(t1, 1e-10f);
    float w2 = 1.f / fmaxf(t2, 1e-10f);
    float inv = 1.f / (w0 + w1 + w2);
    const int gbase = b * SS;
    g_idx[(size_t)b * NQ + q] = make_int4(gbase + i0, gbase + i1, gbase + i2, 0);
    g_wt[(size_t)b * NQ + q]  = make_float4(w0 * inv, w1 * inv, w2 * inv, 0.f);
}

// ---------------------------------------------------------------------------
// Pipelined HMMA GEMM, fp16 2-pass (A single, W = Wh + Wl split).
// 512 threads = 16 warps, warp tile 32x32. CTA tile 128(M) x 128(N),
// N split via grid.y=2. K-chunk 64, double-buffered cp.async + frag db.
//   MODE 0: A=points2 fp32 (K=256), B=w1b -> g_Z fp32
//   MODE 1: A=points1 fp32 (K=128), B=w1a, epi: gather(Z)+bn1+relu -> g_h1 fp16
//   MODE 2: A=g_h1 fp16 tiles (K=256), B=w2, epi: bn2+relu -> out
// h1 tiled layout: row-block (128 rows) stride 65536 B = 4 chunks x 16384 B.
// ---------------------------------------------------------------------------
#define ABYTES 16384
#define BBYTES 16384
#define STAGE  (ABYTES + 2 * BBYTES)   // 48KB: A, B_h, B_l
#define SMEM_SZ (2 * STAGE)            // 96KB

template <int MODE>
__global__ __launch_bounds__(512, 1) void mma_gemm(const float* __restrict__ Ain,
                                                   float* __restrict__ outp) {
    extern __shared__ char smem[];
    const uint32_t sb = smem_u32(smem);

    constexpr int KK  = (MODE == 1) ? 128 : 256;
    constexpr int NCH = KK / 64;

    const int tid = threadIdx.x, wid = tid >> 5, lane = tid & 31;
    const int row0 = blockIdx.x * 128;
    const int col0 = blockIdx.y * 128;
    const int wm = wid & 3, wn = wid >> 2;   // warp tile rows wm*32, cols wn*32

    const __half* BH = (MODE == 0) ? g_w1b_h : (MODE == 1) ? g_w1a_h : g_w2_h;
    const __half* BL = (MODE == 0) ? g_w1b_l : (MODE == 1) ? g_w1a_l : g_w2_l;

    float acc[2][4][4];
#pragma unroll
    for (int mt = 0; mt < 2; mt++)
#pragma unroll
        for (int nt = 0; nt < 4; nt++)
#pragma unroll
            for (int e = 0; e < 4; e++) acc[mt][nt][e] = 0.f;

    // ldmatrix per-lane bases
    const int j = lane >> 3, jlo = j & 1, jhi = j >> 1;
    const uint32_t xr = (uint32_t)(lane & 7) << 4;
    const uint32_t aRow = (uint32_t)(wm * 32 + jlo * 8 + (lane & 7)) * 128u;
    const uint32_t bRow = (uint32_t)(wn * 32 + jlo * 8 + (lane & 7)) * 128u;

    // A fp32 prefetch registers (one 16-float segment per thread)
    const int arow = tid >> 2, asg = tid & 3;
    float4 aNext[4];

    // ---- loaders ----
    auto load_B = [&](int c, int st) {
        const char* srcH = (const char*)BH + c * 32768 + col0 * 128;
        const char* srcL = (const char*)BL + c * 32768 + col0 * 128;
        const uint32_t dH = sb + st * STAGE + ABYTES;
        const uint32_t dL = dH + BBYTES;
#pragma unroll
        for (int p = 0; p < 2; p++) {
            int seg = p * 512 + tid;       // 1024 segs x 16B = 16KB each
            cp16(dH + seg * 16, srcH + seg * 16);
            cp16(dL + seg * 16, srcL + seg * 16);
        }
    };
    auto load_A_cp = [&](int c, int st) {  // MODE 2: tiled fp16 identity copy
        const char* src = (const char*)g_h1 + (size_t)blockIdx.x * 65536 + c * 16384;
        const uint32_t dA = sb + st * STAGE;
#pragma unroll
        for (int p = 0; p < 2; p++) {
            int seg = p * 512 + tid;
            cp16(dA + seg * 16, src + seg * 16);
        }
    };
    auto lda_issue = [&](int c) {          // MODE 0/1: fp32 LDG into regs
        const float* ap = Ain + (size_t)(row0 + arow) * KK + c * 64 + asg * 16;
        aNext[0] = *(const float4*)(ap + 0);
        aNext[1] = *(const float4*)(ap + 4);
        aNext[2] = *(const float4*)(ap + 8);
        aNext[3] = *(const float4*)(ap + 12);
    };
    auto lda_store = [&](int st) {         // fp32->fp16 convert + swizzled STS
        uint32_t h[8];
        h[0] = packh2(aNext[0].x, aNext[0].y); h[1] = packh2(aNext[0].z, aNext[0].w);
        h[2] = packh2(aNext[1].x, aNext[1].y); h[3] = packh2(aNext[1].z, aNext[1].w);
        h[4] = packh2(aNext[2].x, aNext[2].y); h[5] = packh2(aNext[2].z, aNext[2].w);
        h[6] = packh2(aNext[3].x, aNext[3].y); h[7] = packh2(aNext[3].z, aNext[3].w);
        const uint32_t so0 = sw((uint32_t)arow, (uint32_t)asg * 32u);
        const uint32_t so1 = sw((uint32_t)arow, (uint32_t)asg * 32u + 16u);
        char* bp = smem + st * STAGE;
        *(uint4*)(bp + so0) = make_uint4(h[0], h[1], h[2], h[3]);
        *(uint4*)(bp + so1) = make_uint4(h[4], h[5], h[6], h[7]);
    };

    auto ldfrag = [&](uint32_t base, int ks, uint32_t (*ah)[4],
                      uint32_t (*bh)[2], uint32_t (*bl)[2]) {
        const uint32_t kb = ((uint32_t)(ks * 32 + jhi * 16)) ^ xr;
        const uint32_t sA = base;
        const uint32_t sB_h = base + ABYTES, sB_l = sB_h + BBYTES;
        ldm4(ah[0], sA + aRow + kb);
        ldm4(ah[1], sA + aRow + 2048u + kb);
#pragma unroll
        for (int p = 0; p < 2; p++) {
            uint32_t r[4];
            ldm4(r, sB_h + bRow + p * 2048u + kb);
            bh[p * 2 + 0][0] = r[0]; bh[p * 2 + 0][1] = r[2];
            bh[p * 2 + 1][0] = r[1]; bh[p * 2 + 1][1] = r[3];
            ldm4(r, sB_l + bRow + p * 2048u + kb);
            bl[p * 2 + 0][0] = r[0]; bl[p * 2 + 0][1] = r[2];
            bl[p * 2 + 1][0] = r[1]; bl[p * 2 + 1][1] = r[3];
        }
    };

    auto compute = [&](int bufsel) {
        const uint32_t base = sb + bufsel * STAGE;
        uint32_t ahf[2][2][4], bhf[2][4][2], blf[2][4][2];
        ldfrag(base, 0, ahf[0], bhf[0], blf[0]);
#pragma unroll
        for (int ks = 0; ks < 4; ks++) {
            const int cur = ks & 1, nxt = cur ^ 1;
            if (ks < 3) ldfrag(base, ks + 1, ahf[nxt], bhf[nxt], blf[nxt]);
#pragma unroll
            for (int mt = 0; mt < 2; mt++)
#pragma unroll
                for (int nt = 0; nt < 4; nt++)
                    mma16816(acc[mt][nt], ahf[cur][mt], bhf[cur][nt]);
#pragma unroll
            for (int mt = 0; mt < 2; mt++)
#pragma unroll
                for (int nt = 0; nt < 4; nt++)
                    mma16816(acc[mt][nt], ahf[cur][mt], blf[cur][nt]);
        }
    };

    // ---- pipelined mainloop ----
    load_B(0, 0);
    if (MODE == 2) load_A_cp(0, 0);
    CP_COMMIT();
    if (MODE != 2) { lda_issue(0); lda_store(0); }
    CP_WAIT();
    __syncthreads();
    for (int c = 0; c < NCH; c++) {
        const int buf = c & 1;
        if (c + 1 < NCH) {
            load_B(c + 1, buf ^ 1);
            if (MODE == 2) load_A_cp(c + 1, buf ^ 1);
            CP_COMMIT();
            if (MODE != 2) lda_issue(c + 1);
        }
        compute(buf);
        if (c + 1 < NCH) {
            if (MODE != 2) lda_store(buf ^ 1);
            CP_WAIT();
        }
        __syncthreads();
    }

    // ---- epilogue ----
    const int g = lane >> 2, t = lane & 3;
    if (MODE == 0) {
#pragma unroll
        for (int mt = 0; mt < 2; mt++) {
            const int ra = row0 + wm * 32 + mt * 16 + g, rb = ra + 8;
#pragma unroll
            for (int nt = 0; nt < 4; nt++) {
                const int col = col0 + wn * 32 + nt * 8 + 2 * t;
                *(float2*)(g_Z + (size_t)ra * HH + col) = make_float2(acc[mt][nt][0], acc[mt][nt][1]);
                *(float2*)(g_Z + (size_t)rb * HH + col) = make_float2(acc[mt][nt][2], acc[mt][nt][3]);
            }
        }
    } else if (MODE == 2) {
#pragma unroll
        for (int mt = 0; mt < 2; mt++) {
            const int ra = row0 + wm * 32 + mt * 16 + g, rb = ra + 8;
#pragma unroll
            for (int nt = 0; nt < 4; nt++) {
                const int col = col0 + wn * 32 + nt * 8 + 2 * t;
                float sc0 = g_s2[col], sc1 = g_s2[col + 1];
                float bb0 = g_b2[col], bb1 = g_b2[col + 1];
                float v0 = fmaxf(fmaf(acc[mt][nt][0], sc0, bb0), 0.f);
                float v1 = fmaxf(fmaf(acc[mt][nt][1], sc1, bb1), 0.f);
                float v2 = fmaxf(fmaf(acc[mt][nt][2], sc0, bb0), 0.f);
                float v3 = fmaxf(fmaf(acc[mt][nt][3], sc1, bb1), 0.f);
                *(float2*)(outp + (size_t)ra * HH + col) = make_float2(v0, v1);
                *(float2*)(outp + (size_t)rb * HH + col) = make_float2(v2, v3);
            }
        }
    } else {
        // MODE 1: gather from Z, bn1+relu, fp16 convert, stage (32KB), copy out
#pragma unroll
        for (int mt = 0; mt < 2; mt++) {
            const int rla = wm * 32 + mt * 16 + g, rlb = rla + 8;
            const int ra = row0 + rla, rb = row0 + rlb;
            const int4   ia = g_idx[ra], ib = g_idx[rb];
            const float4 wa = g_wt[ra],  wb = g_wt[rb];
#pragma unroll
            for (int nt = 0; nt < 4; nt++) {
                const int lcol = wn * 32 + nt * 8 + 2 * t;
                const int col = col0 + lcol;
                float2 za0 = *(const float2*)(g_Z + (size_t)ia.x * HH + col);
                float2 za1 = *(const float2*)(g_Z + (size_t)ia.y * HH + col);
                float2 za2 = *(const float2*)(g_Z + (size_t)ia.z * HH + col);
                float2 zb0 = *(const float2*)(g_Z + (size_t)ib.x * HH + col);
                float2 zb1 = *(const float2*)(g_Z + (size_t)ib.y * HH + col);
                float2 zb2 = *(const float2*)(g_Z + (size_t)ib.z * HH + col);
                float p0 = fmaf(wa.x, za0.x, fmaf(wa.y, za1.x, wa.z * za2.x));
                float p1 = fmaf(wa.x, za0.y, fmaf(wa.y, za1.y, wa.z * za2.y));
                float p2 = fmaf(wb.x, zb0.x, fmaf(wb.y, zb1.x, wb.z * zb2.x));
                float p3 = fmaf(wb.x, zb0.y, fmaf(wb.y, zb1.y, wb.z * zb2.y));
                float sc0 = g_s1[col], sc1 = g_s1[col + 1];
                float bb0 = g_b1[col], bb1 = g_b1[col + 1];
                float v0 = fmaxf(fmaf(acc[mt][nt][0] + p0, sc0, bb0), 0.f);
                float v1 = fmaxf(fmaf(acc[mt][nt][1] + p1, sc1, bb1), 0.f);
                float v2 = fmaxf(fmaf(acc[mt][nt][2] + p2, sc0, bb0), 0.f);
                float v3 = fmaxf(fmaf(acc[mt][nt][3] + p3, sc1, bb1), 0.f);
                const int lc = lcol >> 6, kin = lcol & 63;
                const uint32_t offa = lc * 16384 + (uint32_t)rla * 128 + (((uint32_t)kin * 2) ^ (((uint32_t)rla & 7) << 4));
                const uint32_t offb = lc * 16384 + (uint32_t)rlb * 128 + (((uint32_t)kin * 2) ^ (((uint32_t)rlb & 7) << 4));
                *(uint32_t*)(smem + offa) = packh2(v0, v1);
                *(uint32_t*)(smem + offb) = packh2(v2, v3);
            }
        }
        __syncthreads();
        // coalesced copy of staged 2 chunks (32KB) to global tiled layout
        // h1 row-block stride = 65536 B; grid.y selects chunks {0,1} or {2,3}
        char* dst = (char*)g_h1 + (size_t)blockIdx.x * 65536 + (size_t)blockIdx.y * 32768;
#pragma unroll
        for (int p = 0; p < 4; p++) {
            int seg = p * 512 + tid;     // 2048 segs x 16B = 32KB
            *(uint4*)(dst + seg * 16) = *(const uint4*)(smem + seg * 16);
        }
    }
}

// ---------------------------------------------------------------------------
// Launch
// ---------------------------------------------------------------------------
extern "C" void kernel_launch(void* const* d_in, const int* in_sizes, int n_in,
                              void* d_out, int out_size) {
    const float* xyz1    = (const float*)d_in[0];
    const float* xyz2    = (const float*)d_in[1];
    const float* points1 = (const float*)d_in[2];
    const float* points2 = (const float*)d_in[3];
    const float* W1      = (const float*)d_in[4];
    const float* gamma1  = (const float*)d_in[5];
    const float* beta1   = (const float*)d_in[6];
    const float* rm1     = (const float*)d_in[7];
    const float* rv1     = (const float*)d_in[8];
    const float* W2      = (const float*)d_in[9];
    const float* gamma2  = (const float*)d_in[10];
    const float* beta2   = (const float*)d_in[11];
    const float* rm2     = (const float*)d_in[12];
    const float* rv2     = (const float*)d_in[13];
    float* out = (float*)d_out;

    cudaFuncSetAttribute(mma_gemm<0>, cudaFuncAttributeMaxDynamicSharedMemorySize, SMEM_SZ);
    cudaFuncSetAttribute(mma_gemm<1>, cudaFuncAttributeMaxDynamicSharedMemorySize, SMEM_SZ);
    cudaFuncSetAttribute(mma_gemm<2>, cudaFuncAttributeMaxDynamicSharedMemorySize, SMEM_SZ);

    bn_prep<<<1, HH>>>(gamma1, beta1, rm1, rv1, gamma2, beta2, rm2, rv2);
    split_weights<<<640, 256>>>(W1, W2);

    // 3-NN indices + weights (global indices)
    nn_idx<<<dim3(BB, NQ / 256), 256>>>(xyz1, xyz2);

    // Z = points2 @ W1b^T
    mma_gemm<0><<<dim3(SROWS / 128, 2), 512, SMEM_SZ>>>(points2, nullptr);

    // h1 = relu(bn1(points1 @ W1a^T + gather(Z)))  -> g_h1 fp16 tiled
    mma_gemm<1><<<dim3(MROWS / 128, 2), 512, SMEM_SZ>>>(points1, nullptr);

    // out = relu(bn2(h1 @ W2^T))
    mma_gemm<2><<<dim3(MROWS / 128, 2), 512, SMEM_SZ>>>(nullptr, out);
}

// round 12
// speedup vs baseline: 2.5039x; 1.1367x over previous
#include <cuda_runtime.h>
#include <cuda_fp16.h>
#include <cstdint>

// Problem constants
#define BB 4
#define NQ 16384
#define SS 2048
#define C1 128
#define C2 256
#define HH 256
#define MROWS (BB * NQ)   // 65536
#define SROWS (BB * SS)   // 8192

// ---------------------------------------------------------------------------
// Device scratch
// ---------------------------------------------------------------------------
__device__ float g_Z[SROWS * HH];                 // 8MB, L2-resident
__device__ __half g_h1[(size_t)MROWS * HH];       // h1 fp16, tiled+swizzled (32MB)
__device__ int4   g_idx[MROWS];                   // 3-NN indices (GLOBAL: b*SS+s)
__device__ float4 g_wt[MROWS];                    // 3-NN weights (normalized)
// weights fp16, tiled+swizzled: [chunk][n 256 rows][64 k, SW128]
__device__ __half g_w1a[HH * C1];
__device__ __half g_w1b[HH * C2];
__device__ __half g_w2[HH * HH];
__device__ float g_s1[HH], g_b1[HH], g_s2[HH], g_b2[HH];

// ---------------------------------------------------------------------------
// Helpers
// ---------------------------------------------------------------------------
__device__ __forceinline__ uint32_t smem_u32(const void* p) {
    uint32_t a;
    asm("{ .reg .u64 t; cvta.to.shared.u64 t, %1; cvt.u32.u64 %0, t; }" : "=r"(a) : "l"(p));
    return a;
}
__device__ __forceinline__ void ldm4(uint32_t* r, uint32_t addr) {
    asm volatile("ldmatrix.sync.aligned.m8n8.x4.shared.b16 {%0,%1,%2,%3}, [%4];"
                 : "=r"(r[0]), "=r"(r[1]), "=r"(r[2]), "=r"(r[3]) : "r"(addr));
}
__device__ __forceinline__ void mma16816(float* c, const uint32_t* a, const uint32_t* b) {
    asm volatile(
        "mma.sync.aligned.m16n8k16.row.col.f32.f16.f16.f32 "
        "{%0,%1,%2,%3}, {%4,%5,%6,%7}, {%8,%9}, {%0,%1,%2,%3};"
        : "+f"(c[0]), "+f"(c[1]), "+f"(c[2]), "+f"(c[3])
        : "r"(a[0]), "r"(a[1]), "r"(a[2]), "r"(a[3]), "r"(b[0]), "r"(b[1]));
}
__device__ __forceinline__ void cp16(uint32_t dst, const void* src) {
    asm volatile("cp.async.cg.shared.global [%0], [%1], 16;" :: "r"(dst), "l"(src));
}
#define CP_COMMIT() asm volatile("cp.async.commit_group;" ::: "memory")
#define CP_WAIT()   asm volatile("cp.async.wait_group 0;" ::: "memory")

__device__ __forceinline__ uint32_t packh2(float a, float b) {
    __half2 h = __floats2half2_rn(a, b);
    return *(uint32_t*)&h;
}
__device__ __forceinline__ uint32_t sw(uint32_t row, uint32_t kb) {
    return row * 128u + (kb ^ ((row & 7u) << 4));
}

// ---------------------------------------------------------------------------
// BN fold
// ---------------------------------------------------------------------------
__global__ void bn_prep(const float* __restrict__ g1, const float* __restrict__ be1,
                        const float* __restrict__ rm1, const float* __restrict__ rv1,
                        const float* __restrict__ g2, const float* __restrict__ be2,
                        const float* __restrict__ rm2, const float* __restrict__ rv2) {
    int h = threadIdx.x;
    float s1 = g1[h] * rsqrtf(rv1[h] + 1e-5f);
    g_s1[h] = s1; g_b1[h] = be1[h] - rm1[h] * s1;
    float s2 = g2[h] * rsqrtf(rv2[h] + 1e-5f);
    g_s2[h] = s2; g_b2[h] = be2[h] - rm2[h] * s2;
}

// ---------------------------------------------------------------------------
// Weight conversion into tiled+swizzled fp16 (single-rounded)
// ---------------------------------------------------------------------------
__global__ __launch_bounds__(256) void conv_weights(const float* __restrict__ W1,
                                                    const float* __restrict__ W2) {
    int i = blockIdx.x * 256 + threadIdx.x;   // 163840 total
    float v; __half* H; int n, k;
    if (i < 32768)       { n = i >> 7; k = i & 127; v = W1[n * 384 + k];             H = g_w1a; }
    else if (i < 98304)  { int j = i - 32768; n = j >> 8; k = j & 255; v = W1[n * 384 + 128 + k]; H = g_w1b; }
    else                 { int j = i - 98304; n = j >> 8; k = j & 255; v = W2[n * 256 + k];       H = g_w2; }
    int chunk = k >> 6, kin = k & 63;
    int boff = n * 128 + ((kin * 2) ^ ((n & 7) << 4));
    H[chunk * 16384 + (boff >> 1)] = __float2half_rn(v);
}

// ---------------------------------------------------------------------------
// 3-NN search: writes GLOBAL idx (b*SS + s) + normalized weights
// ---------------------------------------------------------------------------
__global__ __launch_bounds__(256) void nn_idx(const float* __restrict__ xyz1,
                                              const float* __restrict__ xyz2) {
    __shared__ __align__(16) float4 cand[SS];
    const int b = blockIdx.x, tid = threadIdx.x;
    const float* x2 = xyz2 + (size_t)b * SS * 3;
    for (int s = tid; s < SS; s += 256) {
        float x = x2[s * 3 + 0], y = x2[s * 3 + 1], z = x2[s * 3 + 2];
        cand[s] = make_float4(x, y, z, x * x + y * y + z * z);
    }
    __syncthreads();

    const int q = blockIdx.y * 256 + tid;
    const float* q3 = xyz1 + ((size_t)b * NQ + q) * 3;
    const float qx = q3[0], qy = q3[1], qz = q3[2];
    const float mx = -2.f * qx, my = -2.f * qy, mz = -2.f * qz;

    float d0 = 3.4e38f, d1 = 3.4e38f, d2 = 3.4e38f;
    int i0 = 0, i1 = 0, i2 = 0;
#pragma unroll 4
    for (int s = 0; s < SS; s++) {
        float4 c = cand[s];
        float d = fmaf(mx, c.x, fmaf(my, c.y, fmaf(mz, c.z, c.w)));
        if (d < d2) {
            if (d < d1) {
                d2 = d1; i2 = i1;
                if (d < d0) { d1 = d0; i1 = i0; d0 = d; i0 = s; }
                else        { d1 = d;  i1 = s; }
            } else { d2 = d; i2 = s; }
        }
    }
    const float q2 = qx * qx + qy * qy + qz * qz;
    float t0 = sqrtf(fmaxf(d0 + q2, 0.f));
    float t1 = sqrtf(fmaxf(d1 + q2, 0.f));
    float t2 = sqrtf(fmaxf(d2 + q2, 0.f));
    float w0 = 1.f / fmaxf(t0, 1e-10f);
    float w1 = 1.f / fmaxf(t1, 1e-10f);
    float w2 = 1.f / fmaxf(t2, 1e-10f);
    float inv = 1.f / (w0 + w1 + w2);
    const int gbase = b * SS;
    g_idx[(size_t)b * NQ + q] = make_int4(gbase + i0, gbase + i1, gbase + i2, 0);
    g_wt[(size_t)b * NQ + q]  = make_float4(w0 * inv, w1 * inv, w2 * inv, 0.f);
}

// ---------------------------------------------------------------------------
// Pipelined HMMA GEMM, single-pass fp16. 512 threads = 16 warps, warp 32x32.
// CTA tile 128(M) x 128(N), N split via grid.y=2. K-chunk 64, double-buffered.
//   MODE 0: A=points2 fp32 (K=256), B=w1b -> g_Z fp32
//   MODE 1: A=points1 fp32 (K=128), B=w1a, epi: gather(Z)+bn1+relu -> g_h1 fp16
//   MODE 2: A=g_h1 fp16 tiles (K=256), B=w2, epi: bn2+relu -> out
// h1 tiled layout: row-block (128 rows) stride 65536 B = 4 chunks x 16384 B.
// ---------------------------------------------------------------------------
#define ABYTES 16384
#define BBYTES 16384
#define STAGE  (ABYTES + BBYTES)   // 32KB
#define SMEM_SZ (2 * STAGE)        // 64KB

template <int MODE>
__global__ __launch_bounds__(512, 1) void mma_gemm(const float* __restrict__ Ain,
                                                   float* __restrict__ outp) {
    extern __shared__ char smem[];
    const uint32_t sb = smem_u32(smem);

    constexpr int KK  = (MODE == 1) ? 128 : 256;
    constexpr int NCH = KK / 64;

    const int tid = threadIdx.x, wid = tid >> 5, lane = tid & 31;
    const int row0 = blockIdx.x * 128;
    const int col0 = blockIdx.y * 128;
    const int wm = wid & 3, wn = wid >> 2;   // warp tile rows wm*32, cols wn*32

    const __half* BW = (MODE == 0) ? g_w1b : (MODE == 1) ? g_w1a : g_w2;

    float acc[2][4][4];
#pragma unroll
    for (int mt = 0; mt < 2; mt++)
#pragma unroll
        for (int nt = 0; nt < 4; nt++)
#pragma unroll
            for (int e = 0; e < 4; e++) acc[mt][nt][e] = 0.f;

    // ldmatrix per-lane bases
    const int j = lane >> 3, jlo = j & 1, jhi = j >> 1;
    const uint32_t xr = (uint32_t)(lane & 7) << 4;
    const uint32_t aRow = (uint32_t)(wm * 32 + jlo * 8 + (lane & 7)) * 128u;
    const uint32_t bRow = (uint32_t)(wn * 32 + jlo * 8 + (lane & 7)) * 128u;

    // A fp32 prefetch registers (one 16-float segment per thread)
    const int arow = tid >> 2, asg = tid & 3;
    float4 aNext[4];

    // ---- loaders ----
    auto load_B = [&](int c, int st) {
        const char* src = (const char*)BW + c * 32768 + col0 * 128;
        const uint32_t dB = sb + st * STAGE + ABYTES;
#pragma unroll
        for (int p = 0; p < 2; p++) {
            int seg = p * 512 + tid;       // 1024 segs x 16B = 16KB
            cp16(dB + seg * 16, src + seg * 16);
        }
    };
    auto load_A_cp = [&](int c, int st) {  // MODE 2: tiled fp16 identity copy
        const char* src = (const char*)g_h1 + (size_t)blockIdx.x * 65536 + c * 16384;
        const uint32_t dA = sb + st * STAGE;
#pragma unroll
        for (int p = 0; p < 2; p++) {
            int seg = p * 512 + tid;
            cp16(dA + seg * 16, src + seg * 16);
        }
    };
    auto lda_issue = [&](int c) {          // MODE 0/1: fp32 LDG into regs
        const float* ap = Ain + (size_t)(row0 + arow) * KK + c * 64 + asg * 16;
        aNext[0] = *(const float4*)(ap + 0);
        aNext[1] = *(const float4*)(ap + 4);
        aNext[2] = *(const float4*)(ap + 8);
        aNext[3] = *(const float4*)(ap + 12);
    };
    auto lda_store = [&](int st) {         // fp32->fp16 convert + swizzled STS
        uint32_t h[8];
        h[0] = packh2(aNext[0].x, aNext[0].y); h[1] = packh2(aNext[0].z, aNext[0].w);
        h[2] = packh2(aNext[1].x, aNext[1].y); h[3] = packh2(aNext[1].z, aNext[1].w);
        h[4] = packh2(aNext[2].x, aNext[2].y); h[5] = packh2(aNext[2].z, aNext[2].w);
        h[6] = packh2(aNext[3].x, aNext[3].y); h[7] = packh2(aNext[3].z, aNext[3].w);
        const uint32_t so0 = sw((uint32_t)arow, (uint32_t)asg * 32u);
        const uint32_t so1 = sw((uint32_t)arow, (uint32_t)asg * 32u + 16u);
        char* bp = smem + st * STAGE;
        *(uint4*)(bp + so0) = make_uint4(h[0], h[1], h[2], h[3]);
        *(uint4*)(bp + so1) = make_uint4(h[4], h[5], h[6], h[7]);
    };

    auto ldfrag = [&](uint32_t base, int ks, uint32_t (*ah)[4], uint32_t (*bh)[2]) {
        const uint32_t kb = ((uint32_t)(ks * 32 + jhi * 16)) ^ xr;
        const uint32_t sA = base, sB = base + ABYTES;
        ldm4(ah[0], sA + aRow + kb);
        ldm4(ah[1], sA + aRow + 2048u + kb);
#pragma unroll
        for (int p = 0; p < 2; p++) {
            uint32_t r[4];
            ldm4(r, sB + bRow + p * 2048u + kb);
            bh[p * 2 + 0][0] = r[0]; bh[p * 2 + 0][1] = r[2];
            bh[p * 2 + 1][0] = r[1]; bh[p * 2 + 1][1] = r[3];
        }
    };

    auto compute = [&](int bufsel) {
        const uint32_t base = sb + bufsel * STAGE;
        uint32_t ahf[2][2][4], bhf[2][4][2];
        ldfrag(base, 0, ahf[0], bhf[0]);
#pragma unroll
        for (int ks = 0; ks < 4; ks++) {
            const int cur = ks & 1, nxt = cur ^ 1;
            if (ks < 3) ldfrag(base, ks + 1, ahf[nxt], bhf[nxt]);
#pragma unroll
            for (int mt = 0; mt < 2; mt++)
#pragma unroll
                for (int nt = 0; nt < 4; nt++)
                    mma16816(acc[mt][nt], ahf[cur][mt], bhf[cur][nt]);
        }
    };

    // ---- pipelined mainloop ----
    load_B(0, 0);
    if (MODE == 2) load_A_cp(0, 0);
    CP_COMMIT();
    if (MODE != 2) { lda_issue(0); lda_store(0); }
    CP_WAIT();
    __syncthreads();
    for (int c = 0; c < NCH; c++) {
        const int buf = c & 1;
        if (c + 1 < NCH) {
            load_B(c + 1, buf ^ 1);
            if (MODE == 2) load_A_cp(c + 1, buf ^ 1);
            CP_COMMIT();
            if (MODE != 2) lda_issue(c + 1);
        }
        compute(buf);
        if (c + 1 < NCH) {
            if (MODE != 2) lda_store(buf ^ 1);
            CP_WAIT();
        }
        __syncthreads();
    }

    // ---- epilogue ----
    const int g = lane >> 2, t = lane & 3;
    if (MODE == 0) {
#pragma unroll
        for (int mt = 0; mt < 2; mt++) {
            const int ra = row0 + wm * 32 + mt * 16 + g, rb = ra + 8;
#pragma unroll
            for (int nt = 0; nt < 4; nt++) {
                const int col = col0 + wn * 32 + nt * 8 + 2 * t;
                *(float2*)(g_Z + (size_t)ra * HH + col) = make_float2(acc[mt][nt][0], acc[mt][nt][1]);
                *(float2*)(g_Z + (size_t)rb * HH + col) = make_float2(acc[mt][nt][2], acc[mt][nt][3]);
            }
        }
    } else if (MODE == 2) {
#pragma unroll
        for (int mt = 0; mt < 2; mt++) {
            const int ra = row0 + wm * 32 + mt * 16 + g, rb = ra + 8;
#pragma unroll
            for (int nt = 0; nt < 4; nt++) {
                const int col = col0 + wn * 32 + nt * 8 + 2 * t;
                float sc0 = g_s2[col], sc1 = g_s2[col + 1];
                float bb0 = g_b2[col], bb1 = g_b2[col + 1];
                float v0 = fmaxf(fmaf(acc[mt][nt][0], sc0, bb0), 0.f);
                float v1 = fmaxf(fmaf(acc[mt][nt][1], sc1, bb1), 0.f);
                float v2 = fmaxf(fmaf(acc[mt][nt][2], sc0, bb0), 0.f);
                float v3 = fmaxf(fmaf(acc[mt][nt][3], sc1, bb1), 0.f);
                *(float2*)(outp + (size_t)ra * HH + col) = make_float2(v0, v1);
                *(float2*)(outp + (size_t)rb * HH + col) = make_float2(v2, v3);
            }
        }
    } else {
        // MODE 1: gather from Z, bn1+relu, fp16 convert, stage (32KB), copy out
#pragma unroll
        for (int mt = 0; mt < 2; mt++) {
            const int rla = wm * 32 + mt * 16 + g, rlb = rla + 8;
            const int ra = row0 + rla, rb = row0 + rlb;
            const int4   ia = g_idx[ra], ib = g_idx[rb];
            const float4 wa = g_wt[ra],  wb = g_wt[rb];
#pragma unroll
            for (int nt = 0; nt < 4; nt++) {
                const int lcol = wn * 32 + nt * 8 + 2 * t;
                const int col = col0 + lcol;
                float2 za0 = *(const float2*)(g_Z + (size_t)ia.x * HH + col);
                float2 za1 = *(const float2*)(g_Z + (size_t)ia.y * HH + col);
                float2 za2 = *(const float2*)(g_Z + (size_t)ia.z * HH + col);
                float2 zb0 = *(const float2*)(g_Z + (size_t)ib.x * HH + col);
                float2 zb1 = *(const float2*)(g_Z + (size_t)ib.y * HH + col);
                float2 zb2 = *(const float2*)(g_Z + (size_t)ib.z * HH + col);
                float p0 = fmaf(wa.x, za0.x, fmaf(wa.y, za1.x, wa.z * za2.x));
                float p1 = fmaf(wa.x, za0.y, fmaf(wa.y, za1.y, wa.z * za2.y));
                float p2 = fmaf(wb.x, zb0.x, fmaf(wb.y, zb1.x, wb.z * zb2.x));
                float p3 = fmaf(wb.x, zb0.y, fmaf(wb.y, zb1.y, wb.z * zb2.y));
                float sc0 = g_s1[col], sc1 = g_s1[col + 1];
                float bb0 = g_b1[col], bb1 = g_b1[col + 1];
                float v0 = fmaxf(fmaf(acc[mt][nt][0] + p0, sc0, bb0), 0.f);
                float v1 = fmaxf(fmaf(acc[mt][nt][1] + p1, sc1, bb1), 0.f);
                float v2 = fmaxf(fmaf(acc[mt][nt][2] + p2, sc0, bb0), 0.f);
                float v3 = fmaxf(fmaf(acc[mt][nt][3] + p3, sc1, bb1), 0.f);
                const int lc = lcol >> 6, kin = lcol & 63;
                const uint32_t offa = lc * 16384 + (uint32_t)rla * 128 + (((uint32_t)kin * 2) ^ (((uint32_t)rla & 7) << 4));
                const uint32_t offb = lc * 16384 + (uint32_t)rlb * 128 + (((uint32_t)kin * 2) ^ (((uint32_t)rlb & 7) << 4));
                *(uint32_t*)(smem + offa) = packh2(v0, v1);
                *(uint32_t*)(smem + offb) = packh2(v2, v3);
            }
        }
        __syncthreads();
        // coalesced copy of staged 2 chunks (32KB) to global tiled layout
        // h1 row-block stride = 65536 B; grid.y selects chunks {0,1} or {2,3}
        char* dst = (char*)g_h1 + (size_t)blockIdx.x * 65536 + (size_t)blockIdx.y * 32768;
#pragma unroll
        for (int p = 0; p < 4; p++) {
            int seg = p * 512 + tid;     // 2048 segs x 16B = 32KB
            *(uint4*)(dst + seg * 16) = *(const uint4*)(smem + seg * 16);
        }
    }
}

// ---------------------------------------------------------------------------
// Launch
// ---------------------------------------------------------------------------
extern "C" void kernel_launch(void* const* d_in, const int* in_sizes, int n_in,
                              void* d_out, int out_size) {
    const float* xyz1    = (const float*)d_in[0];
    const float* xyz2    = (const float*)d_in[1];
    const float* points1 = (const float*)d_in[2];
    const float* points2 = (const float*)d_in[3];
    const float* W1      = (const float*)d_in[4];
    const float* gamma1  = (const float*)d_in[5];
    const float* beta1   = (const float*)d_in[6];
    const float* rm1     = (const float*)d_in[7];
    const float* rv1     = (const float*)d_in[8];
    const float* W2      = (const float*)d_in[9];
    const float* gamma2  = (const float*)d_in[10];
    const float* beta2   = (const float*)d_in[11];
    const float* rm2     = (const float*)d_in[12];
    const float* rv2     = (const float*)d_in[13];
    float* out = (float*)d_out;

    cudaFuncSetAttribute(mma_gemm<0>, cudaFuncAttributeMaxDynamicSharedMemorySize, SMEM_SZ);
    cudaFuncSetAttribute(mma_gemm<1>, cudaFuncAttributeMaxDynamicSharedMemorySize, SMEM_SZ);
    cudaFuncSetAttribute(mma_gemm<2>, cudaFuncAttributeMaxDynamicSharedMemorySize, SMEM_SZ);

    bn_prep<<<1, HH>>>(gamma1, beta1, rm1, rv1, gamma2, beta2, rm2, rv2);
    conv_weights<<<640, 256>>>(W1, W2);

    // 3-NN indices + weights (global indices)
    nn_idx<<<dim3(BB, NQ / 256), 256>>>(xyz1, xyz2);

    // Z = points2 @ W1b^T
    mma_gemm<0><<<dim3(SROWS / 128, 2), 512, SMEM_SZ>>>(points2, nullptr);

    // h1 = relu(bn1(points1 @ W1a^T + gather(Z)))  -> g_h1 fp16 tiled
    mma_gemm<1><<<dim3(MROWS / 128, 2), 512, SMEM_SZ>>>(points1, nullptr);

    // out = relu(bn2(h1 @ W2^T))
    mma_gemm<2><<<dim3(MROWS / 128, 2), 512, SMEM_SZ>>>(nullptr, out);
}

// round 14
// speedup vs baseline: 2.6113x; 1.0429x over previous
#include <cuda_runtime.h>
#include <cuda_fp16.h>
#include <cstdint>

// Problem constants
#define BB 4
#define NQ 16384
#define SS 2048
#define C1 128
#define C2 256
#define HH 256
#define MROWS (BB * NQ)   // 65536
#define SROWS (BB * SS)   // 8192

// ---------------------------------------------------------------------------
// Device scratch
// ---------------------------------------------------------------------------
__device__ float g_Z[SROWS * HH];                 // 8MB, L2-resident
__device__ __half g_h1[(size_t)MROWS * HH];       // h1 fp16 tiled (32MB), rb stride 65536B
__device__ __half g_p1[(size_t)MROWS * C1];       // points1 fp16 tiled (16MB), rb stride 32768B
__device__ __half g_p2[SROWS * C2];               // points2 fp16 tiled (4MB),  rb stride 65536B
__device__ int4   g_idx[MROWS];                   // 3-NN indices (GLOBAL: b*SS+s)
__device__ float4 g_wt[MROWS];                    // 3-NN weights (normalized)
// weights fp16, tiled+swizzled: [chunk][n 256 rows][64 k, SW128]
__device__ __half g_w1a[HH * C1];
__device__ __half g_w1b[HH * C2];
__device__ __half g_w2[HH * HH];
__device__ float g_s1[HH], g_b1[HH], g_s2[HH], g_b2[HH];

// ---------------------------------------------------------------------------
// Helpers
// ---------------------------------------------------------------------------
__device__ __forceinline__ uint32_t smem_u32(const void* p) {
    uint32_t a;
    asm("{ .reg .u64 t; cvta.to.shared.u64 t, %1; cvt.u32.u64 %0, t; }" : "=r"(a) : "l"(p));
    return a;
}
__device__ __forceinline__ void ldm4(uint32_t* r, uint32_t addr) {
    asm volatile("ldmatrix.sync.aligned.m8n8.x4.shared.b16 {%0,%1,%2,%3}, [%4];"
                 : "=r"(r[0]), "=r"(r[1]), "=r"(r[2]), "=r"(r[3]) : "r"(addr));
}
__device__ __forceinline__ void mma16816(float* c, const uint32_t* a, const uint32_t* b) {
    asm volatile(
        "mma.sync.aligned.m16n8k16.row.col.f32.f16.f16.f32 "
        "{%0,%1,%2,%3}, {%4,%5,%6,%7}, {%8,%9}, {%0,%1,%2,%3};"
        : "+f"(c[0]), "+f"(c[1]), "+f"(c[2]), "+f"(c[3])
        : "r"(a[0]), "r"(a[1]), "r"(a[2]), "r"(a[3]), "r"(b[0]), "r"(b[1]));
}
__device__ __forceinline__ void cp16(uint32_t dst, const void* src) {
    asm volatile("cp.async.cg.shared.global [%0], [%1], 16;" :: "r"(dst), "l"(src));
}
#define CP_COMMIT() asm volatile("cp.async.commit_group;" ::: "memory")
#define CP_WAIT()   asm volatile("cp.async.wait_group 0;" ::: "memory")

__device__ __forceinline__ uint32_t packh2(float a, float b) {
    __half2 h = __floats2half2_rn(a, b);
    return *(uint32_t*)&h;
}

// ---------------------------------------------------------------------------
// BN fold
// ---------------------------------------------------------------------------
__global__ void bn_prep(const float* __restrict__ g1, const float* __restrict__ be1,
                        const float* __restrict__ rm1, const float* __restrict__ rv1,
                        const float* __restrict__ g2, const float* __restrict__ be2,
                        const float* __restrict__ rm2, const float* __restrict__ rv2) {
    int h = threadIdx.x;
    float s1 = g1[h] * rsqrtf(rv1[h] + 1e-5f);
    g_s1[h] = s1; g_b1[h] = be1[h] - rm1[h] * s1;
    float s2 = g2[h] * rsqrtf(rv2[h] + 1e-5f);
    g_s2[h] = s2; g_b2[h] = be2[h] - rm2[h] * s2;
}

// ---------------------------------------------------------------------------
// Weight conversion into tiled+swizzled fp16
// ---------------------------------------------------------------------------
__global__ __launch_bounds__(256) void conv_weights(const float* __restrict__ W1,
                                                    const float* __restrict__ W2) {
    int i = blockIdx.x * 256 + threadIdx.x;   // 163840 total
    float v; __half* H; int n, k;
    if (i < 32768)       { n = i >> 7; k = i & 127; v = W1[n * 384 + k];             H = g_w1a; }
    else if (i < 98304)  { int j = i - 32768; n = j >> 8; k = j & 255; v = W1[n * 384 + 128 + k]; H = g_w1b; }
    else                 { int j = i - 98304; n = j >> 8; k = j & 255; v = W2[n * 256 + k];       H = g_w2; }
    int chunk = k >> 6, kin = k & 63;
    int boff = n * 128 + ((kin * 2) ^ ((n & 7) << 4));
    H[chunk * 16384 + (boff >> 1)] = __float2half_rn(v);
}

// ---------------------------------------------------------------------------
// Activation conversion: points1/points2 fp32 -> fp16 tiled+swizzled
// Each thread: one 8-half segment (16B). p1: 16 segs/row; p2: 32 segs/row.
// ---------------------------------------------------------------------------
#define P1SEGS (MROWS * (C1 / 8))    // 1048576
#define P2SEGS (SROWS * (C2 / 8))    // 262144

__global__ __launch_bounds__(256) void conv_points(const float* __restrict__ p1,
                                                   const float* __restrict__ p2) {
    int i = blockIdx.x * 256 + threadIdx.x;
    const float* src; char* dst; int r, s, KKr; size_t rbs;
    if (i < P1SEGS) { r = i >> 4; s = i & 15; src = p1; dst = (char*)g_p1; KKr = C1; rbs = 32768; }
    else {
        int j = i - P1SEGS;
        if (j >= P2SEGS) return;
        r = j >> 5; s = j & 31; src = p2; dst = (char*)g_p2; KKr = C2; rbs = 65536;
    }
    const int k0 = s * 8;
    const float* ap = src + (size_t)r * KKr + k0;
    float4 a0 = *(const float4*)(ap + 0);
    float4 a1 = *(const float4*)(ap + 4);
    uint4 h = make_uint4(packh2(a0.x, a0.y), packh2(a0.z, a0.w),
                         packh2(a1.x, a1.y), packh2(a1.z, a1.w));
    const int rb = r >> 7, rl = r & 127, chunk = k0 >> 6, kin = k0 & 63;
    const size_t off = (size_t)rb * rbs + chunk * 16384
                     + rl * 128 + (((uint32_t)kin * 2) ^ (((uint32_t)rl & 7) << 4));
    *(uint4*)(dst + off) = h;
}

// ---------------------------------------------------------------------------
// 3-NN search: writes GLOBAL idx (b*SS + s) + normalized weights
// ---------------------------------------------------------------------------
__global__ __launch_bounds__(256) void nn_idx(const float* __restrict__ xyz1,
                                              const float* __restrict__ xyz2) {
    __shared__ __align__(16) float4 cand[SS];
    const int b = blockIdx.x, tid = threadIdx.x;
    const float* x2 = xyz2 + (size_t)b * SS * 3;
    for (int s = tid; s < SS; s += 256) {
        float x = x2[s * 3 + 0], y = x2[s * 3 + 1], z = x2[s * 3 + 2];
        cand[s] = make_float4(x, y, z, x * x + y * y + z * z);
    }
    __syncthreads();

    const int q = blockIdx.y * 256 + tid;
    const float* q3 = xyz1 + ((size_t)b * NQ + q) * 3;
    const float qx = q3[0], qy = q3[1], qz = q3[2];
    const float mx = -2.f * qx, my = -2.f * qy, mz = -2.f * qz;

    float d0 = 3.4e38f, d1 = 3.4e38f, d2 = 3.4e38f;
    int i0 = 0, i1 = 0, i2 = 0;
#pragma unroll 4
    for (int s = 0; s < SS; s++) {
        float4 c = cand[s];
        float d = fmaf(mx, c.x, fmaf(my, c.y, fmaf(mz, c.z, c.w)));
        if (d < d2) {
            if (d < d1) {
                d2 = d1; i2 = i1;
                if (d < d0) { d1 = d0; i1 = i0; d0 = d; i0 = s; }
                else        { d1 = d;  i1 = s; }
            } else { d2 = d; i2 = s; }
        }
    }
    const float q2 = qx * qx + qy * qy + qz * qz;
    float t0 = sqrtf(fmaxf(d0 + q2, 0.f));
    float t1 = sqrtf(fmaxf(d1 + q2, 0.f));
    float t2 = sqrtf(fmaxf(d2 + q2, 0.f));
    float w0 = 1.f / fmaxf(t0, 1e-10f);
    float w1 = 1.f / fmaxf(t1, 1e-10f);
    float w2 = 1.f / fmaxf(t2, 1e-10f);
    float inv = 1.f / (w0 + w1 + w2);
    const int gbase = b * SS;
    g_idx[(size_t)b * NQ + q] = make_int4(gbase + i0, gbase + i1, gbase + i2, 0);
    g_wt[(size_t)b * NQ + q]  = make_float4(w0 * inv, w1 * inv, w2 * inv, 0.f);
}

// ---------------------------------------------------------------------------
// Pipelined HMMA GEMM, single-pass fp16, ALL operands via cp.async from tiled
// fp16 global arrays. 512 threads = 16 warps, warp tile 32x32, 2 CTAs/SM.
// CTA tile 128(M) x 128(N), N split via grid.y=2. K-chunk 64, double-buffered.
//   MODE 0: A=g_p2 (K=256, rbs 65536), B=w1b -> g_Z fp32
//   MODE 1: A=g_p1 (K=128, rbs 32768), B=w1a, epi: gather(Z)+bn1+relu -> g_h1
//   MODE 2: A=g_h1 (K=256, rbs 65536), B=w2,  epi: bn2+relu -> out
// ---------------------------------------------------------------------------
#define ABYTES 16384
#define BBYTES 16384
#define STAGE  (ABYTES + BBYTES)   // 32KB
#define SMEM_SZ (2 * STAGE)        // 64KB

template <int MODE>
__global__ __launch_bounds__(512, 2) void mma_gemm(float* __restrict__ outp) {
    extern __shared__ char smem[];
    const uint32_t sb = smem_u32(smem);

    constexpr int KK  = (MODE == 1) ? 128 : 256;
    constexpr int NCH = KK / 64;
    constexpr size_t RBS = (MODE == 1) ? 32768 : 65536;

    const int tid = threadIdx.x, wid = tid >> 5, lane = tid & 31;
    const int row0 = blockIdx.x * 128;
    const int col0 = blockIdx.y * 128;
    const int wm = wid & 3, wn = wid >> 2;   // warp tile rows wm*32, cols wn*32

    const __half* BW = (MODE == 0) ? g_w1b : (MODE == 1) ? g_w1a : g_w2;
    const __half* AW = (MODE == 0) ? g_p2  : (MODE == 1) ? g_p1  : g_h1;

    float acc[2][4][4];
#pragma unroll
    for (int mt = 0; mt < 2; mt++)
#pragma unroll
        for (int nt = 0; nt < 4; nt++)
#pragma unroll
            for (int e = 0; e < 4; e++) acc[mt][nt][e] = 0.f;

    // ldmatrix per-lane bases
    const int j = lane >> 3, jlo = j & 1, jhi = j >> 1;
    const uint32_t xr = (uint32_t)(lane & 7) << 4;
    const uint32_t aRow = (uint32_t)(wm * 32 + jlo * 8 + (lane & 7)) * 128u;
    const uint32_t bRow = (uint32_t)(wn * 32 + jlo * 8 + (lane & 7)) * 128u;

    // ---- loaders (pure cp.async identity copies) ----
    auto load_AB = [&](int c, int st) {
        const char* srcA = (const char*)AW + (size_t)blockIdx.x * RBS + c * 16384;
        const char* srcB = (const char*)BW + c * 32768 + col0 * 128;
        const uint32_t dA = sb + st * STAGE;
        const uint32_t dB = dA + ABYTES;
#pragma unroll
        for (int p = 0; p < 2; p++) {
            int seg = p * 512 + tid;       // 1024 segs x 16B = 16KB each
            cp16(dA + seg * 16, srcA + seg * 16);
            cp16(dB + seg * 16, srcB + seg * 16);
        }
    };

    auto compute = [&](int bufsel) {
        const uint32_t base = sb + bufsel * STAGE;
        const uint32_t sA = base, sB = base + ABYTES;
#pragma unroll
        for (int ks = 0; ks < 4; ks++) {
            const uint32_t kb = ((uint32_t)(ks * 32 + jhi * 16)) ^ xr;
            uint32_t ah[2][4], bh[4][2];
            ldm4(ah[0], sA + aRow + kb);
            ldm4(ah[1], sA + aRow + 2048u + kb);
#pragma unroll
            for (int p = 0; p < 2; p++) {
                uint32_t r[4];
                ldm4(r, sB + bRow + p * 2048u + kb);
                bh[p * 2 + 0][0] = r[0]; bh[p * 2 + 0][1] = r[2];
                bh[p * 2 + 1][0] = r[1]; bh[p * 2 + 1][1] = r[3];
            }
#pragma unroll
            for (int mt = 0; mt < 2; mt++)
#pragma unroll
                for (int nt = 0; nt < 4; nt++)
                    mma16816(acc[mt][nt], ah[mt], bh[nt]);
        }
    };

    // ---- pipelined mainloop ----
    load_AB(0, 0);
    CP_COMMIT();
    CP_WAIT();
    __syncthreads();
    for (int c = 0; c < NCH; c++) {
        const int buf = c & 1;
        if (c + 1 < NCH) {
            load_AB(c + 1, buf ^ 1);
            CP_COMMIT();
        }
        compute(buf);
        if (c + 1 < NCH) CP_WAIT();
        __syncthreads();
    }

    // ---- epilogue ----
    const int g = lane >> 2, t = lane & 3;
    if (MODE == 0) {
#pragma unroll
        for (int mt = 0; mt < 2; mt++) {
            const int ra = row0 + wm * 32 + mt * 16 + g, rb = ra + 8;
#pragma unroll
            for (int nt = 0; nt < 4; nt++) {
                const int col = col0 + wn * 32 + nt * 8 + 2 * t;
                *(float2*)(g_Z + (size_t)ra * HH + col) = make_float2(acc[mt][nt][0], acc[mt][nt][1]);
                *(float2*)(g_Z + (size_t)rb * HH + col) = make_float2(acc[mt][nt][2], acc[mt][nt][3]);
            }
        }
    } else if (MODE == 2) {
#pragma unroll
        for (int mt = 0; mt < 2; mt++) {
            const int ra = row0 + wm * 32 + mt * 16 + g, rb = ra + 8;
#pragma unroll
            for (int nt = 0; nt < 4; nt++) {
                const int col = col0 + wn * 32 + nt * 8 + 2 * t;
                float sc0 = g_s2[col], sc1 = g_s2[col + 1];
                float bb0 = g_b2[col], bb1 = g_b2[col + 1];
                float v0 = fmaxf(fmaf(acc[mt][nt][0], sc0, bb0), 0.f);
                float v1 = fmaxf(fmaf(acc[mt][nt][1], sc1, bb1), 0.f);
                float v2 = fmaxf(fmaf(acc[mt][nt][2], sc0, bb0), 0.f);
                float v3 = fmaxf(fmaf(acc[mt][nt][3], sc1, bb1), 0.f);
                *(float2*)(outp + (size_t)ra * HH + col) = make_float2(v0, v1);
                *(float2*)(outp + (size_t)rb * HH + col) = make_float2(v2, v3);
            }
        }
    } else {
        // MODE 1: gather from Z, bn1+relu, fp16 convert, stage (32KB), copy out
#pragma unroll
        for (int mt = 0; mt < 2; mt++) {
            const int rla = wm * 32 + mt * 16 + g, rlb = rla + 8;
            const int ra = row0 + rla, rb = row0 + rlb;
            const int4   ia = g_idx[ra], ib = g_idx[rb];
            const float4 wa = g_wt[ra],  wb = g_wt[rb];
#pragma unroll
            for (int nt = 0; nt < 4; nt++) {
                const int lcol = wn * 32 + nt * 8 + 2 * t;
                const int col = col0 + lcol;
                float2 za0 = *(const float2*)(g_Z + (size_t)ia.x * HH + col);
                float2 za1 = *(const float2*)(g_Z + (size_t)ia.y * HH + col);
                float2 za2 = *(const float2*)(g_Z + (size_t)ia.z * HH + col);
                float2 zb0 = *(const float2*)(g_Z + (size_t)ib.x * HH + col);
                float2 zb1 = *(const float2*)(g_Z + (size_t)ib.y * HH + col);
                float2 zb2 = *(const float2*)(g_Z + (size_t)ib.z * HH + col);
                float p0 = fmaf(wa.x, za0.x, fmaf(wa.y, za1.x, wa.z * za2.x));
                float p1 = fmaf(wa.x, za0.y, fmaf(wa.y, za1.y, wa.z * za2.y));
                float p2 = fmaf(wb.x, zb0.x, fmaf(wb.y, zb1.x, wb.z * zb2.x));
                float p3 = fmaf(wb.x, zb0.y, fmaf(wb.y, zb1.y, wb.z * zb2.y));
                float sc0 = g_s1[col], sc1 = g_s1[col + 1];
                float bb0 = g_b1[col], bb1 = g_b1[col + 1];
                float v0 = fmaxf(fmaf(acc[mt][nt][0] + p0, sc0, bb0), 0.f);
                float v1 = fmaxf(fmaf(acc[mt][nt][1] + p1, sc1, bb1), 0.f);
                float v2 = fmaxf(fmaf(acc[mt][nt][2] + p2, sc0, bb0), 0.f);
                float v3 = fmaxf(fmaf(acc[mt][nt][3] + p3, sc1, bb1), 0.f);
                const int lc = lcol >> 6, kin = lcol & 63;
                const uint32_t offa = lc * 16384 + (uint32_t)rla * 128 + (((uint32_t)kin * 2) ^ (((uint32_t)rla & 7) << 4));
                const uint32_t offb = lc * 16384 + (uint32_t)rlb * 128 + (((uint32_t)kin * 2) ^ (((uint32_t)rlb & 7) << 4));
                *(uint32_t*)(smem + offa) = packh2(v0, v1);
                *(uint32_t*)(smem + offb) = packh2(v2, v3);
            }
        }
        __syncthreads();
        // coalesced copy of staged 2 chunks (32KB) to global tiled layout
        // h1 row-block stride = 65536 B; grid.y selects chunks {0,1} or {2,3}
        char* dst = (char*)g_h1 + (size_t)blockIdx.x * 65536 + (size_t)blockIdx.y * 32768;
#pragma unroll
        for (int p = 0; p < 4; p++) {
            int seg = p * 512 + tid;     // 2048 segs x 16B = 32KB
            *(uint4*)(dst + seg * 16) = *(const uint4*)(smem + seg * 16);
        }
    }
}

// ---------------------------------------------------------------------------
// Launch
// ---------------------------------------------------------------------------
extern "C" void kernel_launch(void* const* d_in, const int* in_sizes, int n_in,
                              void* d_out, int out_size) {
    const float* xyz1    = (const float*)d_in[0];
    const float* xyz2    = (const float*)d_in[1];
    const float* points1 = (const float*)d_in[2];
    const float* points2 = (const float*)d_in[3];
    const float* W1      = (const float*)d_in[4];
    const float* gamma1  = (const float*)d_in[5];
    const float* beta1   = (const float*)d_in[6];
    const float* rm1     = (const float*)d_in[7];
    const float* rv1     = (const float*)d_in[8];
    const float* W2      = (const float*)d_in[9];
    const float* gamma2  = (const float*)d_in[10];
    const float* beta2   = (const float*)d_in[11];
    const float* rm2     = (const float*)d_in[12];
    const float* rv2     = (const float*)d_in[13];
    float* out = (float*)d_out;

    cudaFuncSetAttribute(mma_gemm<0>, cudaFuncAttributeMaxDynamicSharedMemorySize, SMEM_SZ);
    cudaFuncSetAttribute(mma_gemm<1>, cudaFuncAttributeMaxDynamicSharedMemorySize, SMEM_SZ);
    cudaFuncSetAttribute(mma_gemm<2>, cudaFuncAttributeMaxDynamicSharedMemorySize, SMEM_SZ);

    bn_prep<<<1, HH>>>(gamma1, beta1, rm1, rv1, gamma2, beta2, rm2, rv2);
    conv_weights<<<640, 256>>>(W1, W2);
    conv_points<<<(P1SEGS + P2SEGS + 255) / 256, 256>>>(points1, points2);

    // 3-NN indices + weights (global indices)
    nn_idx<<<dim3(BB, NQ / 256), 256>>>(xyz1, xyz2);

    // Z = points2 @ W1b^T
    mma_gemm<0><<<dim3(SROWS / 128, 2), 512, SMEM_SZ>>>(nullptr);

    // h1 = relu(bn1(points1 @ W1a^T + gather(Z)))  -> g_h1 fp16 tiled
    mma_gemm<1><<<dim3(MROWS / 128, 2), 512, SMEM_SZ>>>(nullptr);

    // out = relu(bn2(h1 @ W2^T))
    mma_gemm<2><<<dim3(MROWS / 128, 2), 512, SMEM_SZ>>>(out);
}